// round 13
// baseline (speedup 1.0000x reference)
#include <cuda_runtime.h>
#include <cstdint>

#define BB 256       // batch
#define OO 128       // positions / out features
#define IIN (OO*128) // 16384
#define EIGEN_KC 248 // Eigen threaded gebp depth panel (validated R5)
#define NPAN 67      // ceil(16384/248)
#define EPSW 1e-4f
#define QCAP 4096

// Scratch (allocation-free rule: __device__ globals)
__device__ float    g_T[(size_t)BB*OO*OO];   // T[b][pos][o], 16.8 MB
__device__ float    g_G[(size_t)OO*BB*OO];   // gumbel noise, 16.8 MB
__device__ float    g_PF[(size_t)BB*OO*OO];  // PF[b][j][o] p-trajectory, 16.8 MB
__device__ uint32_t g_keys[OO][2];
__device__ int      g_poss[BB*OO];           // chosen position per (b, j)
__device__ int      g_inv[BB*OO];            // step at which column o was chosen
__device__ float    g_lsj[BB*OO];            // per-step logp pieces
__device__ int      g_errj[BB*OO];           // per-step error bits
__device__ int      g_nwork;                 // resolver worklist size
__device__ int4     g_queue[QCAP];           // (b, j, ostar, 0)

// ---------------- Threefry2x32 (bit-exact JAX, partitionable) ----------------
__device__ __forceinline__ uint32_t rotl32(uint32_t x, int d) {
    return (x << d) | (x >> (32 - d));
}

__device__ __forceinline__ void tf2x32(uint32_t k0, uint32_t k1,
                                       uint32_t x0, uint32_t x1,
                                       uint32_t& o0, uint32_t& o1) {
    uint32_t k2 = k0 ^ k1 ^ 0x1BD11BDAu;
    x0 += k0; x1 += k1;
#define TF_R(r) { x0 += x1; x1 = rotl32(x1, r); x1 ^= x0; }
    TF_R(13) TF_R(15) TF_R(26) TF_R(6)
    x0 += k1;  x1 += k2 + 1u;
    TF_R(17) TF_R(29) TF_R(16) TF_R(24)
    x0 += k2;  x1 += k0 + 2u;
    TF_R(13) TF_R(15) TF_R(26) TF_R(6)
    x0 += k0;  x1 += k1 + 3u;
    TF_R(17) TF_R(29) TF_R(16) TF_R(24)
    x0 += k1;  x1 += k2 + 4u;
    TF_R(13) TF_R(15) TF_R(26) TF_R(6)
    x0 += k2;  x1 += k0 + 5u;
#undef TF_R
    o0 = x0; o1 = x1;
}

__device__ __forceinline__ float bits_to_gumbel(uint32_t bits) {
    float f = __uint_as_float((bits >> 9) | 0x3F800000u) - 1.0f;
    float u = fmaxf(1.17549435e-38f, f);
    float t = -logf(u);
    return -logf(t);
}

__global__ __launch_bounds__(128) void k_keys() {
    int j = threadIdx.x;
    uint32_t o0, o1;
    tf2x32(0u, 42u, 0u, (uint32_t)j, o0, o1);
    g_keys[j][0] = o0;
    g_keys[j][1] = o1;
    if (j == 0) g_nwork = 0;
}

__global__ __launch_bounds__(256) void k_gumbel() {
    int i = blockIdx.x * 256 + threadIdx.x;
    int j = blockIdx.y;
    uint32_t o0, o1;
    tf2x32(g_keys[j][0], g_keys[j][1], 0u, (uint32_t)i, o0, o1);
    g_G[(size_t)j * (BB * OO) + i] = bits_to_gumbel(o0 ^ o1);
}

// ---------------- per-position contribution matrix ----------------
__global__ __launch_bounds__(256) void k_T(const float* __restrict__ enc,
                                           const float* __restrict__ W) {
    extern __shared__ float sm[];
    float* Wt = sm;                 // [128][129]
    float* E  = sm + 128 * 129;     // [32][128]
    const int pos = blockIdx.x;
    const int b0  = blockIdx.y * 32;
    const int t   = threadIdx.x;

    for (int i = t; i < 128 * 128; i += 256) {
        int o = i >> 7, d = i & 127;
        Wt[d * 129 + o] = W[(size_t)o * IIN + pos * 128 + d];
    }
    for (int i = t; i < 32 * 128; i += 256) {
        int bb = i >> 7, d = i & 127;
        E[i] = enc[(size_t)(b0 + bb) * IIN + pos * 128 + d];
    }
    __syncthreads();

    const int o  = t & 127;
    const int bg = t >> 7;
    float acc[16];
#pragma unroll
    for (int k = 0; k < 16; k++) acc[k] = 0.f;
    for (int d4 = 0; d4 < 128; d4 += 4) {
        float w0 = Wt[(d4 + 0) * 129 + o];
        float w1 = Wt[(d4 + 1) * 129 + o];
        float w2 = Wt[(d4 + 2) * 129 + o];
        float w3 = Wt[(d4 + 3) * 129 + o];
#pragma unroll
        for (int k = 0; k < 16; k++) {
            float4 e = *(const float4*)&E[(bg * 16 + k) * 128 + d4];
            float a = acc[k];
            a = fmaf(e.x, w0, a);
            a = fmaf(e.y, w1, a);
            a = fmaf(e.z, w2, a);
            a = fmaf(e.w, w3, a);
            acc[k] = a;
        }
    }
#pragma unroll
    for (int k = 0; k < 16; k++) {
        int b = b0 + bg * 16 + k;
        g_T[((size_t)b * 128 + pos) * 128 + o] = acc[k];
    }
}

__device__ __forceinline__ uint32_t ord32(float f) {
    uint32_t fb = __float_as_uint(f);
    return (fb & 0x80000000u) ? ~fb : (fb | 0x80000000u);
}

// ---------------- kernel A: serial chains, 2 independent rows per warp ------
__global__ __launch_bounds__(32) void k_sample(const float* __restrict__ bias,
                                               float* __restrict__ out,
                                               int out_size) {
    extern __shared__ float sT[];   // 2 x 64KB: T tiles for rows b0, b0+1
    const int b0   = blockIdx.x * 2;
    const int lane = threadIdx.x;

    // stage both tiles
#pragma unroll
    for (int r = 0; r < 2; r++) {
        const float4* src = (const float4*)&g_T[(size_t)(b0 + r) * OO * OO];
        float4* dst = (float4*)(sT + r * (OO * OO));
#pragma unroll 8
        for (int i = lane; i < 4096; i += 32) dst[i] = src[i];
    }
    __syncwarp();

    // lane owns columns o = 4*lane + q in both rows; Kahan fp32 state per row
    float s[2][4], c[2][4];
    {
        float4 bv = *(const float4*)&bias[4 * lane];
#pragma unroll
        for (int r = 0; r < 2; r++) {
            s[r][0] = bv.x; s[r][1] = bv.y; s[r][2] = bv.z; s[r][3] = bv.w;
#pragma unroll
            for (int q = 0; q < 4; q++) c[r][q] = 0.f;
        }
    }
    for (int pos = 0; pos < 128; pos++) {
#pragma unroll
        for (int r = 0; r < 2; r++) {
            float4 tv = *(const float4*)&sT[r * (OO*OO) + pos * 128 + 4 * lane];
            float tq[4] = {tv.x, tv.y, tv.z, tv.w};
#pragma unroll
            for (int q = 0; q < 4; q++) {
                float y = tq[q] - c[r][q];
                float t = s[r][q] + y;
                c[r][q] = (t - s[r][q]) - y;
                s[r][q] = t;
            }
        }
    }

    unsigned avail[2] = {0xFu, 0xFu};
    float4 gcur[2];
#pragma unroll
    for (int r = 0; r < 2; r++)
        gcur[r] = *(const float4*)&g_G[(size_t)(b0 + r) * 128 + 4 * lane];

    for (int j = 0; j < 128; j++) {
        float4 gnxt[2];
#pragma unroll
        for (int r = 0; r < 2; r++) {
            gnxt[r] = make_float4(0.f, 0.f, 0.f, 0.f);
            if (j < 127)
                gnxt[r] = *(const float4*)
                    &g_G[((size_t)(j + 1) * BB + (b0 + r)) * 128 + 4 * lane];
        }

        // PF rows (off critical path)
#pragma unroll
        for (int r = 0; r < 2; r++)
            *(float4*)&g_PF[((size_t)(b0 + r) * 128 + j) * 128 + 4 * lane] =
                make_float4(s[r][0], s[r][1], s[r][2], s[r][3]);

        // local best per row (double-float key)
        unsigned long long bk[2] = {0ULL, 0ULL};
        int bi[2] = {0, 0};
#pragma unroll
        for (int r = 0; r < 2; r++) {
            float gq[4] = {gcur[r].x, gcur[r].y, gcur[r].z, gcur[r].w};
#pragma unroll
            for (int q = 0; q < 4; q++) {
                if (avail[r] & (1u << q)) {
                    float a = s[r][q], g = gq[q];
                    float th = a + g;
                    float bp = th - a;
                    float e  = (a - (th - bp)) + (g - bp);
                    float te = e - c[r][q];
                    float hi = th + te;
                    float lo = te - (hi - th);
                    unsigned long long k =
                        ((unsigned long long)ord32(hi) << 32) | ord32(lo);
                    if (k > bk[r]) { bk[r] = k; bi[r] = 4 * lane + q; }
                }
            }
        }

        // argmax per row: REDUX fast path, exact butterfly on hi-tie
        int pos[2];
#pragma unroll
        for (int r = 0; r < 2; r++) {
            uint32_t hi32 = (uint32_t)(bk[r] >> 32);
            uint32_t mh = __reduce_max_sync(0xffffffffu, hi32);
            unsigned msk = __ballot_sync(0xffffffffu, hi32 == mh);
            if (__popc(msk) == 1) {
                pos[r] = __shfl_sync(0xffffffffu, bi[r], __ffs(msk) - 1);
            } else {
                unsigned long long kk = bk[r]; int ii = bi[r];
#pragma unroll
                for (int off = 16; off; off >>= 1) {
                    unsigned long long ok = __shfl_xor_sync(0xffffffffu, kk, off);
                    int oi = __shfl_xor_sync(0xffffffffu, ii, off);
                    if (ok > kk || (ok == kk && oi < ii)) { kk = ok; ii = oi; }
                }
                pos[r] = ii;
            }
        }

#pragma unroll
        for (int r = 0; r < 2; r++) {
            if ((pos[r] >> 2) == lane) avail[r] &= ~(1u << (pos[r] & 3));
            if (lane == 0) {
                g_poss[(b0 + r) * 128 + j] = pos[r];
                g_inv[(b0 + r) * 128 + pos[r]] = j;
                if (out_size >= BB * OO)
                    out[(b0 + r) * 128 + (127 - j)] = (float)pos[r];
            }
        }

        // Kahan subtract T[pos][o] per row
#pragma unroll
        for (int r = 0; r < 2; r++) {
            float4 tv = *(const float4*)&sT[r * (OO*OO) + pos[r] * 128 + 4 * lane];
            float tq[4] = {tv.x, tv.y, tv.z, tv.w};
#pragma unroll
            for (int q = 0; q < 4; q++) {
                float y = (-tq[q]) - c[r][q];
                float t = s[r][q] + y;
                c[r][q] = (t - s[r][q]) - y;
                s[r][q] = t;
            }
            gcur[r] = gnxt[r];
        }
    }
}

// ---------------- kernel B: one warp per (b, j), lean strict counting -------
__global__ __launch_bounds__(128) void k_probe(const float* __restrict__ bias) {
    __shared__ __align__(16) float srow[4][128];
    const int t = threadIdx.x, w = t >> 5, lane = t & 31;
    const int item = blockIdx.x * 4 + w;         // 8192 blocks * 4 warps = 32768
    const int b = item >> 7, j = item & 127;

    float4 v = *(const float4*)&g_PF[((size_t)b * 128 + j) * 128 + 4 * lane];
    *(float4*)&srow[w][4 * lane] = v;
    float pf0 = v.x, pf1 = v.y, pf2 = v.z, pf3 = v.w;
    int4 iv = *(const int4*)&g_inv[b * 128 + 4 * lane];
    int av0 = iv.x >= j, av1 = iv.y >= j, av2 = iv.z >= j, av3 = iv.w >= j;
    __syncwarp();

    int cs0 = 0, cs1 = 0, cs2 = 0, cs3 = 0;
    {
        const float4* kr = (const float4*)srow[w];
#pragma unroll 8
        for (int iv4 = 0; iv4 < 32; iv4++) {
            float4 x = kr[iv4];
            cs0 += (x.x > pf0) + (x.y > pf0) + (x.z > pf0) + (x.w > pf0);
            cs1 += (x.x > pf1) + (x.y > pf1) + (x.z > pf1) + (x.w > pf1);
            cs2 += (x.x > pf2) + (x.y > pf2) + (x.z > pf2) + (x.w > pf2);
            cs3 += (x.x > pf3) + (x.y > pf3) + (x.z > pf3) + (x.w > pf3);
        }
    }
    const int o0 = 4 * lane;
    int c1 = 999;
    if (cs0 == j) c1 = min(c1, o0);
    if (cs1 == j) c1 = min(c1, o0 + 1);
    if (cs2 == j) c1 = min(c1, o0 + 2);
    if (cs3 == j) c1 = min(c1, o0 + 3);
#pragma unroll
    for (int off = 16; off; off >>= 1)
        c1 = min(c1, __shfl_xor_sync(0xffffffffu, c1, off));

    int ostar = c1;
    if (c1 == 999) {  // exact stable-rank fallback (duplicates straddle; ~never)
        int ce0 = 0, ce1 = 0, ce2 = 0, ce3 = 0;
        for (int i = 0; i < 128; i++) {
            float x = srow[w][i];
            ce0 += (x == pf0) && (i < o0);
            ce1 += (x == pf1) && (i < o0 + 1);
            ce2 += (x == pf2) && (i < o0 + 2);
            ce3 += (x == pf3) && (i < o0 + 3);
        }
        int c2 = 999;
        if (cs0 + ce0 == j) c2 = min(c2, o0);
        if (cs1 + ce1 == j) c2 = min(c2, o0 + 1);
        if (cs2 + ce2 == j) c2 = min(c2, o0 + 2);
        if (cs3 + ce3 == j) c2 = min(c2, o0 + 3);
#pragma unroll
        for (int off = 16; off; off >>= 1)
            c2 = min(c2, __shfl_xor_sync(0xffffffffu, c2, off));
        ostar = c2;
    }

    const int srcl = ostar >> 2, qsel = ostar & 3;
    float pown = (qsel == 0) ? pf0 : (qsel == 1) ? pf1 : (qsel == 2) ? pf2 : pf3;
    int   aown = (qsel == 0) ? av0 : (qsel == 1) ? av1 : (qsel == 2) ? av2 : av3;
    float pj  = __shfl_sync(0xffffffffu, pown, srcl);
    int   avj = __shfl_sync(0xffffffffu, aown, srcl);

    int mix = ((fabsf(pf0 - pj) < EPSW) && (av0 != avj)) |
              ((fabsf(pf1 - pj) < EPSW) && (av1 != avj)) |
              ((fabsf(pf2 - pj) < EPSW) && (av2 != avj)) |
              ((fabsf(pf3 - pj) < EPSW) && (av3 != avj));
    mix = __any_sync(0xffffffffu, mix);

    float m = -__int_as_float(0x7F800000);
    if (av0) m = fmaxf(m, pf0);
    if (av1) m = fmaxf(m, pf1);
    if (av2) m = fmaxf(m, pf2);
    if (av3) m = fmaxf(m, pf3);
#pragma unroll
    for (int off = 16; off; off >>= 1)
        m = fmaxf(m, __shfl_xor_sync(0xffffffffu, m, off));
    float ss = 0.f;
    if (av0) ss += expf(pf0 - m);
    if (av1) ss += expf(pf1 - m);
    if (av2) ss += expf(pf2 - m);
    if (av3) ss += expf(pf3 - m);
#pragma unroll
    for (int off = 16; off; off >>= 1)
        ss += __shfl_xor_sync(0xffffffffu, ss, off);

    const int posj = g_poss[b * 128 + j];
    const int srcp = posj >> 2, qp = posj & 3;
    float ppw = (qp == 0) ? pf0 : (qp == 1) ? pf1 : (qp == 2) ? pf2 : pf3;
    float ppos = __shfl_sync(0xffffffffu, ppw, srcp);

    if (lane == 0) {
        g_lsj[b * 128 + j]  = ppos - m - logf(ss);
        g_errj[b * 128 + j] = avj ? 0 : 1;
        if (mix) {
            int idx = atomicAdd(&g_nwork, 1);
            if (idx < QCAP) g_queue[idx] = make_int4(b, j, ostar, 0);
        }
    }
}

// ---------------- kernel C: exact resolver, panel-parallel Eigen emulation --
__global__ __launch_bounds__(128) void k_resolve(const float* __restrict__ enc,
                                                 const float* __restrict__ W,
                                                 const float* __restrict__ bias) {
    extern __shared__ float sEnc[];  // [16384]
    __shared__ float row[128];
    __shared__ int   inv[128];
    __shared__ int   incl[128];
    __shared__ float s_pan[NPAN];
    __shared__ unsigned long long key2s[128];
    const int t = threadIdx.x;
    int n = g_nwork; if (n > QCAP) n = QCAP;

    for (int it = blockIdx.x; it < n; it += gridDim.x) {
        int4 e = g_queue[it];
        const int b = e.x, j = e.y, ostar = e.z;
        row[t] = g_PF[((size_t)b * 128 + j) * 128 + t];
        inv[t] = g_inv[b * 128 + t];
        {
            const float4* src = (const float4*)(enc + (size_t)b * IIN);
            float4* dst = (float4*)sEnc;
            for (int i = t; i < IIN / 4; i += 128) dst[i] = src[i];
        }
        __syncthreads();
        float pj = row[ostar];
        int inclt = fabsf(row[t] - pj) < EPSW;
        incl[t] = inclt;
        __syncthreads();

        for (int o = 0; o < 128; o++) {
            if (!incl[o]) continue;
            const float* W_o = W + (size_t)o * IIN;
            if (t < NPAN) {
                int k0 = t * EIGEN_KC;
                int k1 = k0 + EIGEN_KC; if (k1 > IIN) k1 = IIN;
                float acc = 0.f;
                int k = k0;
                while (k < k1) {
                    int pos = k >> 7;
                    int pe  = (pos + 1) << 7; if (pe > k1) pe = k1;
                    if (inv[pos] >= j) {
                        for (; k < pe; k++)
                            acc = fmaf(sEnc[k], W_o[k], acc);
                    } else {
                        k = pe;
                    }
                }
                s_pan[t] = acc;
            }
            __syncthreads();
            if (t == 0) {
                float total = 0.f;
                for (int p = 0; p < NPAN; p++) total += s_pan[p];  // ascending: exact
                float ev = total + bias[o];
                key2s[o] = ((unsigned long long)ord32(ev) << 32) | (unsigned)(127 - o);
            }
            __syncthreads();
        }

        if (inclt) {
            unsigned long long key2 = key2s[t];
            int cm = 0;
            for (int i = 0; i < 128; i++) {
                if (incl[i]) cm += (key2s[i] > key2);
                else         cm += (row[i] > pj);
            }
            if (cm == j) g_errj[b * 128 + j] = (inv[t] >= j) ? 0 : 1;
        }
        __syncthreads();
    }
}

// ---------------- kernel D: final reductions (warp per row) -----------------
__global__ __launch_bounds__(256) void k_final(float* __restrict__ out,
                                               int out_size) {
    const int t = threadIdx.x, lane = t & 31, w = t >> 5;
    const int b = blockIdx.x * 8 + w;           // 32 blocks * 8 warps = 256
    float4 lv = *(const float4*)&g_lsj[b * 128 + 4 * lane];
    int4   ev = *(const int4*)&g_errj[b * 128 + 4 * lane];
    double acc = (double)lv.x + (double)lv.y + (double)lv.z + (double)lv.w;
    int ec = ev.x + ev.y + ev.z + ev.w;
#pragma unroll
    for (int off = 16; off; off >>= 1) {
        acc += __shfl_xor_sync(0xffffffffu, acc, off);
        ec  += __shfl_xor_sync(0xffffffffu, ec, off);
    }
    if (lane == 0) {
        if (out_size >= BB * OO + 2 * BB) {
            out[BB * OO + b]      = (float)acc;
            out[BB * OO + BB + b] = (float)ec;
        } else if (out_size >= BB * OO + BB) {
            out[BB * OO + b] = (float)acc;
        }
    }
}

// ---------------- launch ----------------
extern "C" void kernel_launch(void* const* d_in, const int* in_sizes, int n_in,
                              void* d_out, int out_size) {
    const float* enc  = (const float*)d_in[0];   // [256,128,128]
    const float* W    = (const float*)d_in[1];   // [128,16384]
    const float* bias = (const float*)d_in[2];   // [128]
    float* out = (float*)d_out;

    const int smemT = (128 * 129 + 32 * 128) * (int)sizeof(float);  // 82432 B
    cudaFuncSetAttribute(k_T, cudaFuncAttributeMaxDynamicSharedMemorySize, smemT);
    cudaFuncSetAttribute(k_sample, cudaFuncAttributeMaxDynamicSharedMemorySize,
                         2 * 65536);
    cudaFuncSetAttribute(k_resolve, cudaFuncAttributeMaxDynamicSharedMemorySize, 65536);

    k_keys<<<1, 128>>>();
    k_T<<<dim3(128, 8), 256, smemT>>>(enc, W);
    k_gumbel<<<dim3(128, 128), 256>>>();
    k_sample<<<128, 32, 2 * 65536>>>(bias, out, out_size);
    k_probe<<<8192, 128>>>(bias);
    k_resolve<<<256, 128, 65536>>>(enc, W, bias);
    k_final<<<32, 256>>>(out, out_size);
}

// round 14
// speedup vs baseline: 1.0348x; 1.0348x over previous
#include <cuda_runtime.h>
#include <cstdint>

#define BB 256       // batch
#define OO 128       // positions / out features
#define IIN (OO*128) // 16384
#define EIGEN_KC 248 // Eigen threaded gebp depth panel (validated R5)
#define NPAN 67      // ceil(16384/248)
#define EPSW 1e-4f
#define QCAP 4096
#define TPITCH 132   // smem row pitch (floats) for k_T tiles

// Scratch (allocation-free rule: __device__ globals)
__device__ float    g_T[(size_t)BB*OO*OO];   // T[b][pos][o], 16.8 MB
__device__ float    g_G[(size_t)OO*BB*OO];   // gumbel noise, 16.8 MB
__device__ float    g_PF[(size_t)BB*OO*OO];  // PF[b][j][o] p-trajectory, 16.8 MB
__device__ int      g_poss[BB*OO];           // chosen position per (b, j)
__device__ int      g_inv[BB*OO];            // step at which column o was chosen
__device__ float    g_lsj[BB*OO];            // per-step logp pieces
__device__ int      g_errj[BB*OO];           // per-step error bits
__device__ int      g_nwork;                 // resolver worklist size
__device__ int4     g_queue[QCAP];           // (b, j, ostar, 0)

// ---------------- Threefry2x32 (bit-exact JAX, partitionable) ----------------
__device__ __forceinline__ uint32_t rotl32(uint32_t x, int d) {
    return (x << d) | (x >> (32 - d));
}

__device__ __forceinline__ void tf2x32(uint32_t k0, uint32_t k1,
                                       uint32_t x0, uint32_t x1,
                                       uint32_t& o0, uint32_t& o1) {
    uint32_t k2 = k0 ^ k1 ^ 0x1BD11BDAu;
    x0 += k0; x1 += k1;
#define TF_R(r) { x0 += x1; x1 = rotl32(x1, r); x1 ^= x0; }
    TF_R(13) TF_R(15) TF_R(26) TF_R(6)
    x0 += k1;  x1 += k2 + 1u;
    TF_R(17) TF_R(29) TF_R(16) TF_R(24)
    x0 += k2;  x1 += k0 + 2u;
    TF_R(13) TF_R(15) TF_R(26) TF_R(6)
    x0 += k0;  x1 += k1 + 3u;
    TF_R(17) TF_R(29) TF_R(16) TF_R(24)
    x0 += k1;  x1 += k2 + 4u;
    TF_R(13) TF_R(15) TF_R(26) TF_R(6)
    x0 += k2;  x1 += k0 + 5u;
#undef TF_R
    o0 = x0; o1 = x1;
}

__device__ __forceinline__ float bits_to_gumbel(uint32_t bits) {
    float f = __uint_as_float((bits >> 9) | 0x3F800000u) - 1.0f;
    float u = fmaxf(1.17549435e-38f, f);
    float t = -logf(u);
    return -logf(t);
}

// keys computed inline: keys[j] = threefry((0,42),(0,j)); bits = o0^o1 of
// threefry(keys[j],(0,i)) — identical values to the validated split kernels.
__global__ __launch_bounds__(256) void k_gumbel() {
    int i = blockIdx.x * 256 + threadIdx.x;
    int j = blockIdx.y;
    uint32_t ka, kb;
    tf2x32(0u, 42u, 0u, (uint32_t)j, ka, kb);
    uint32_t o0, o1;
    tf2x32(ka, kb, 0u, (uint32_t)i, o0, o1);
    g_G[(size_t)j * (BB * OO) + i] = bits_to_gumbel(o0 ^ o1);
}

// ---------------- per-position contribution matrix ----------------
// T[b][pos][o] = sum_d enc[b,pos,d] * W[o, pos*128+d]
// 4o x 4b register tile, d-major float4 smem loads, pitch-132 rows.
// FMA order per (b,o): single accumulator, d ascending -> bit-identical T.
__global__ __launch_bounds__(256) void k_T(const float* __restrict__ enc,
                                           const float* __restrict__ W) {
    extern __shared__ float sm[];
    float* Wt = sm;                      // [128][TPITCH] (o rows, d-major)
    float* E  = sm + 128 * TPITCH;       // [32][TPITCH]  (b rows, d-major)
    const int pos = blockIdx.x;
    const int b0  = blockIdx.y * 32;
    const int t   = threadIdx.x;

    if (pos == 0 && blockIdx.y == 0 && t == 0) g_nwork = 0;

    for (int i = t; i < 128 * 32; i += 256) {
        int o = i >> 5, d4 = i & 31;
        *(float4*)&Wt[o * TPITCH + d4 * 4] =
            *(const float4*)&W[(size_t)o * IIN + pos * 128 + d4 * 4];
    }
    for (int i = t; i < 32 * 32; i += 256) {
        int bb = i >> 5, d4 = i & 31;
        *(float4*)&E[bb * TPITCH + d4 * 4] =
            *(const float4*)&enc[(size_t)(b0 + bb) * IIN + pos * 128 + d4 * 4];
    }
    __syncthreads();

    const int og = t >> 3, bg = t & 7;   // 32 o-groups x 8 b-groups
    const int o0 = og * 4, bq0 = bg * 4;
    float acc[4][4];
#pragma unroll
    for (int bi = 0; bi < 4; bi++)
#pragma unroll
        for (int oi = 0; oi < 4; oi++) acc[bi][oi] = 0.f;

    for (int d4 = 0; d4 < 32; d4++) {
        float4 wv[4], ev[4];
#pragma unroll
        for (int oi = 0; oi < 4; oi++)
            wv[oi] = *(const float4*)&Wt[(o0 + oi) * TPITCH + d4 * 4];
#pragma unroll
        for (int bi = 0; bi < 4; bi++)
            ev[bi] = *(const float4*)&E[(bq0 + bi) * TPITCH + d4 * 4];
#pragma unroll
        for (int bi = 0; bi < 4; bi++)
#pragma unroll
            for (int oi = 0; oi < 4; oi++) {
                float a = acc[bi][oi];
                a = fmaf(ev[bi].x, wv[oi].x, a);
                a = fmaf(ev[bi].y, wv[oi].y, a);
                a = fmaf(ev[bi].z, wv[oi].z, a);
                a = fmaf(ev[bi].w, wv[oi].w, a);
                acc[bi][oi] = a;
            }
    }

    // stage to smem (reuse Wt region as Tout[32][128]) for coalesced stores
    __syncthreads();
    float* Tout = Wt;
#pragma unroll
    for (int bi = 0; bi < 4; bi++)
#pragma unroll
        for (int oi = 0; oi < 4; oi++)
            Tout[(bq0 + bi) * 128 + (o0 + oi)] = acc[bi][oi];
    __syncthreads();
    for (int i = t; i < 32 * 32; i += 256) {
        int bb = i >> 5, d4 = i & 31;
        *(float4*)&g_T[((size_t)(b0 + bb) * 128 + pos) * 128 + d4 * 4] =
            *(const float4*)&Tout[bb * 128 + d4 * 4];
    }
}

__device__ __forceinline__ uint32_t ord32(float f) {
    uint32_t fb = __float_as_uint(f);
    return (fb & 0x80000000u) ? ~fb : (fb | 0x80000000u);
}

// ---------------- kernel A: serial sampling chain (warp per row) ------------
__global__ __launch_bounds__(32) void k_sample(const float* __restrict__ bias,
                                               float* __restrict__ out,
                                               int out_size) {
    extern __shared__ float sT[];   // 64KB: T[pos][o]
    const int b    = blockIdx.x;
    const int lane = threadIdx.x;
    const float* Tg = &g_T[(size_t)b * OO * OO];

    {
        const float4* src = (const float4*)Tg;
        float4* dst = (float4*)sT;
#pragma unroll 8
        for (int i = lane; i < 4096; i += 32) dst[i] = src[i];
    }
    __syncwarp();

    // lane owns columns o = 4*lane + q ; Kahan-compensated fp32 p
    float s[4], c[4];
    {
        float4 bv = *(const float4*)&bias[4 * lane];
        s[0] = bv.x; s[1] = bv.y; s[2] = bv.z; s[3] = bv.w;
#pragma unroll
        for (int q = 0; q < 4; q++) c[q] = 0.f;
    }
    for (int pos = 0; pos < 128; pos++) {
        float4 tv = *(const float4*)&sT[pos * 128 + 4 * lane];
        float tq[4] = {tv.x, tv.y, tv.z, tv.w};
#pragma unroll
        for (int q = 0; q < 4; q++) {
            float y = tq[q] - c[q];
            float t = s[q] + y;
            c[q] = (t - s[q]) - y;
            s[q] = t;
        }
    }

    unsigned avail = 0xFu;
    float4 gcur = *(const float4*)&g_G[(size_t)b * 128 + 4 * lane];

    for (int j = 0; j < 128; j++) {
        float4 gnxt = make_float4(0.f, 0.f, 0.f, 0.f);
        if (j < 127)
            gnxt = *(const float4*)&g_G[((size_t)(j + 1) * BB + b) * 128 + 4 * lane];
        float gq[4] = {gcur.x, gcur.y, gcur.z, gcur.w};

        // materialize PF row (off critical path)
        *(float4*)&g_PF[((size_t)b * 128 + j) * 128 + 4 * lane] =
            make_float4(s[0], s[1], s[2], s[3]);

        // lane-local best over 4 owned columns: double-float (hi,lo) key -> u64
        unsigned long long bk = 0ULL; int bi = 0;
#pragma unroll
        for (int q = 0; q < 4; q++) {
            if (avail & (1u << q)) {
                float a = s[q], g = gq[q];
                float th = a + g;
                float bp = th - a;
                float e  = (a - (th - bp)) + (g - bp);
                float te = e - c[q];
                float hi = th + te;
                float lo = te - (hi - th);
                unsigned long long k =
                    ((unsigned long long)ord32(hi) << 32) | ord32(lo);
                if (k > bk) { bk = k; bi = 4 * lane + q; }
            }
        }

        // fast argmax: single REDUX on the hi 32 bits; butterfly only on hi-tie
        int pos;
        {
            uint32_t hi32 = (uint32_t)(bk >> 32);
            uint32_t mh = __reduce_max_sync(0xffffffffu, hi32);
            unsigned msk = __ballot_sync(0xffffffffu, hi32 == mh);
            if (__popc(msk) == 1) {
                pos = __shfl_sync(0xffffffffu, bi, __ffs(msk) - 1);
            } else {
                // exact (hi,lo,idx) butterfly — rare hi-collision path
#pragma unroll
                for (int off = 16; off; off >>= 1) {
                    unsigned long long ok = __shfl_xor_sync(0xffffffffu, bk, off);
                    int oi = __shfl_xor_sync(0xffffffffu, bi, off);
                    if (ok > bk || (ok == bk && oi < bi)) { bk = ok; bi = oi; }
                }
                pos = bi;
            }
        }

        if ((pos >> 2) == lane) avail &= ~(1u << (pos & 3));
        if (lane == 0) {
            g_poss[b * 128 + j] = pos;
            g_inv[b * 128 + pos] = j;
            if (out_size >= BB * OO)
                out[b * 128 + (127 - j)] = (float)pos;
        }

        float4 tv = *(const float4*)&sT[pos * 128 + 4 * lane];
        float tq[4] = {tv.x, tv.y, tv.z, tv.w};
#pragma unroll
        for (int q = 0; q < 4; q++) {
            float y = (-tq[q]) - c[q];
            float t = s[q] + y;
            c[q] = (t - s[q]) - y;
            s[q] = t;
        }
        gcur = gnxt;
    }
}

// ---------------- kernel B: one warp per (b, j), lean strict counting -------
__global__ __launch_bounds__(128) void k_probe(const float* __restrict__ bias) {
    __shared__ __align__(16) float srow[4][128];
    const int t = threadIdx.x, w = t >> 5, lane = t & 31;
    const int item = blockIdx.x * 4 + w;         // 8192 blocks * 4 warps = 32768
    const int b = item >> 7, j = item & 127;

    float4 v = *(const float4*)&g_PF[((size_t)b * 128 + j) * 128 + 4 * lane];
    *(float4*)&srow[w][4 * lane] = v;
    float pf0 = v.x, pf1 = v.y, pf2 = v.z, pf3 = v.w;
    int4 iv = *(const int4*)&g_inv[b * 128 + 4 * lane];
    int av0 = iv.x >= j, av1 = iv.y >= j, av2 = iv.z >= j, av3 = iv.w >= j;
    __syncwarp();

    int cs0 = 0, cs1 = 0, cs2 = 0, cs3 = 0;
    {
        const float4* kr = (const float4*)srow[w];
#pragma unroll 8
        for (int iv4 = 0; iv4 < 32; iv4++) {
            float4 x = kr[iv4];
            cs0 += (x.x > pf0) + (x.y > pf0) + (x.z > pf0) + (x.w > pf0);
            cs1 += (x.x > pf1) + (x.y > pf1) + (x.z > pf1) + (x.w > pf1);
            cs2 += (x.x > pf2) + (x.y > pf2) + (x.z > pf2) + (x.w > pf2);
            cs3 += (x.x > pf3) + (x.y > pf3) + (x.z > pf3) + (x.w > pf3);
        }
    }
    const int o0 = 4 * lane;
    int c1 = 999;
    if (cs0 == j) c1 = min(c1, o0);
    if (cs1 == j) c1 = min(c1, o0 + 1);
    if (cs2 == j) c1 = min(c1, o0 + 2);
    if (cs3 == j) c1 = min(c1, o0 + 3);
#pragma unroll
    for (int off = 16; off; off >>= 1)
        c1 = min(c1, __shfl_xor_sync(0xffffffffu, c1, off));

    int ostar = c1;
    if (c1 == 999) {  // exact stable-rank fallback (duplicates straddle; ~never)
        int ce0 = 0, ce1 = 0, ce2 = 0, ce3 = 0;
        for (int i = 0; i < 128; i++) {
            float x = srow[w][i];
            ce0 += (x == pf0) && (i < o0);
            ce1 += (x == pf1) && (i < o0 + 1);
            ce2 += (x == pf2) && (i < o0 + 2);
            ce3 += (x == pf3) && (i < o0 + 3);
        }
        int c2 = 999;
        if (cs0 + ce0 == j) c2 = min(c2, o0);
        if (cs1 + ce1 == j) c2 = min(c2, o0 + 1);
        if (cs2 + ce2 == j) c2 = min(c2, o0 + 2);
        if (cs3 + ce3 == j) c2 = min(c2, o0 + 3);
#pragma unroll
        for (int off = 16; off; off >>= 1)
            c2 = min(c2, __shfl_xor_sync(0xffffffffu, c2, off));
        ostar = c2;
    }

    const int srcl = ostar >> 2, qsel = ostar & 3;
    float pown = (qsel == 0) ? pf0 : (qsel == 1) ? pf1 : (qsel == 2) ? pf2 : pf3;
    int   aown = (qsel == 0) ? av0 : (qsel == 1) ? av1 : (qsel == 2) ? av2 : av3;
    float pj  = __shfl_sync(0xffffffffu, pown, srcl);
    int   avj = __shfl_sync(0xffffffffu, aown, srcl);

    int mix = ((fabsf(pf0 - pj) < EPSW) && (av0 != avj)) |
              ((fabsf(pf1 - pj) < EPSW) && (av1 != avj)) |
              ((fabsf(pf2 - pj) < EPSW) && (av2 != avj)) |
              ((fabsf(pf3 - pj) < EPSW) && (av3 != avj));
    mix = __any_sync(0xffffffffu, mix);

    float m = -__int_as_float(0x7F800000);
    if (av0) m = fmaxf(m, pf0);
    if (av1) m = fmaxf(m, pf1);
    if (av2) m = fmaxf(m, pf2);
    if (av3) m = fmaxf(m, pf3);
#pragma unroll
    for (int off = 16; off; off >>= 1)
        m = fmaxf(m, __shfl_xor_sync(0xffffffffu, m, off));
    float ss = 0.f;
    if (av0) ss += expf(pf0 - m);
    if (av1) ss += expf(pf1 - m);
    if (av2) ss += expf(pf2 - m);
    if (av3) ss += expf(pf3 - m);
#pragma unroll
    for (int off = 16; off; off >>= 1)
        ss += __shfl_xor_sync(0xffffffffu, ss, off);

    const int posj = g_poss[b * 128 + j];
    const int srcp = posj >> 2, qp = posj & 3;
    float ppw = (qp == 0) ? pf0 : (qp == 1) ? pf1 : (qp == 2) ? pf2 : pf3;
    float ppos = __shfl_sync(0xffffffffu, ppw, srcp);

    if (lane == 0) {
        g_lsj[b * 128 + j]  = ppos - m - logf(ss);
        g_errj[b * 128 + j] = avj ? 0 : 1;
        if (mix) {
            int idx = atomicAdd(&g_nwork, 1);
            if (idx < QCAP) g_queue[idx] = make_int4(b, j, ostar, 0);
        }
    }
}

// ---------------- kernel C: exact resolver, panel-parallel Eigen emulation --
__global__ __launch_bounds__(128) void k_resolve(const float* __restrict__ enc,
                                                 const float* __restrict__ W,
                                                 const float* __restrict__ bias) {
    extern __shared__ float sEnc[];  // [16384]
    __shared__ float row[128];
    __shared__ int   inv[128];
    __shared__ int   incl[128];
    __shared__ float s_pan[NPAN];
    __shared__ unsigned long long key2s[128];
    const int t = threadIdx.x;
    int n = g_nwork; if (n > QCAP) n = QCAP;

    for (int it = blockIdx.x; it < n; it += gridDim.x) {
        int4 e = g_queue[it];
        const int b = e.x, j = e.y, ostar = e.z;
        row[t] = g_PF[((size_t)b * 128 + j) * 128 + t];
        inv[t] = g_inv[b * 128 + t];
        {
            const float4* src = (const float4*)(enc + (size_t)b * IIN);
            float4* dst = (float4*)sEnc;
            for (int i = t; i < IIN / 4; i += 128) dst[i] = src[i];
        }
        __syncthreads();
        float pj = row[ostar];
        int inclt = fabsf(row[t] - pj) < EPSW;
        incl[t] = inclt;
        __syncthreads();

        for (int o = 0; o < 128; o++) {
            if (!incl[o]) continue;
            const float* W_o = W + (size_t)o * IIN;
            if (t < NPAN) {
                int k0 = t * EIGEN_KC;
                int k1 = k0 + EIGEN_KC; if (k1 > IIN) k1 = IIN;
                float acc = 0.f;
                int k = k0;
                while (k < k1) {
                    int pos = k >> 7;
                    int pe  = (pos + 1) << 7; if (pe > k1) pe = k1;
                    if (inv[pos] >= j) {
                        for (; k < pe; k++)
                            acc = fmaf(sEnc[k], W_o[k], acc);
                    } else {
                        k = pe;
                    }
                }
                s_pan[t] = acc;
            }
            __syncthreads();
            if (t == 0) {
                float total = 0.f;
                for (int p = 0; p < NPAN; p++) total += s_pan[p];  // ascending: exact
                float ev = total + bias[o];
                key2s[o] = ((unsigned long long)ord32(ev) << 32) | (unsigned)(127 - o);
            }
            __syncthreads();
        }

        if (inclt) {
            unsigned long long key2 = key2s[t];
            int cm = 0;
            for (int i = 0; i < 128; i++) {
                if (incl[i]) cm += (key2s[i] > key2);
                else         cm += (row[i] > pj);
            }
            if (cm == j) g_errj[b * 128 + j] = (inv[t] >= j) ? 0 : 1;
        }
        __syncthreads();
    }
}

// ---------------- kernel D: final reductions (warp per row) -----------------
__global__ __launch_bounds__(256) void k_final(float* __restrict__ out,
                                               int out_size) {
    const int t = threadIdx.x, lane = t & 31, w = t >> 5;
    const int b = blockIdx.x * 8 + w;           // 32 blocks * 8 warps = 256
    float4 lv = *(const float4*)&g_lsj[b * 128 + 4 * lane];
    int4   ev = *(const int4*)&g_errj[b * 128 + 4 * lane];
    double acc = (double)lv.x + (double)lv.y + (double)lv.z + (double)lv.w;
    int ec = ev.x + ev.y + ev.z + ev.w;
#pragma unroll
    for (int off = 16; off; off >>= 1) {
        acc += __shfl_xor_sync(0xffffffffu, acc, off);
        ec  += __shfl_xor_sync(0xffffffffu, ec, off);
    }
    if (lane == 0) {
        if (out_size >= BB * OO + 2 * BB) {
            out[BB * OO + b]      = (float)acc;
            out[BB * OO + BB + b] = (float)ec;
        } else if (out_size >= BB * OO + BB) {
            out[BB * OO + b] = (float)acc;
        }
    }
}

// ---------------- launch ----------------
extern "C" void kernel_launch(void* const* d_in, const int* in_sizes, int n_in,
                              void* d_out, int out_size) {
    const float* enc  = (const float*)d_in[0];   // [256,128,128]
    const float* W    = (const float*)d_in[1];   // [128,16384]
    const float* bias = (const float*)d_in[2];   // [128]
    float* out = (float*)d_out;

    const int smemT = (128 + 32) * TPITCH * (int)sizeof(float);  // 84480 B
    cudaFuncSetAttribute(k_T, cudaFuncAttributeMaxDynamicSharedMemorySize, smemT);
    cudaFuncSetAttribute(k_sample, cudaFuncAttributeMaxDynamicSharedMemorySize, 65536);
    cudaFuncSetAttribute(k_resolve, cudaFuncAttributeMaxDynamicSharedMemorySize, 65536);

    k_T<<<dim3(128, 8), 256, smemT>>>(enc, W);
    k_gumbel<<<dim3(128, 128), 256>>>();
    k_sample<<<256, 32, 65536>>>(bias, out, out_size);
    k_probe<<<8192, 128>>>(bias);
    k_resolve<<<256, 128, 65536>>>(enc, W, bias);
    k_final<<<32, 256>>>(out, out_size);
}

// round 15
// speedup vs baseline: 1.1401x; 1.1018x over previous
#include <cuda_runtime.h>
#include <cstdint>

#define BB 256       // batch
#define OO 128       // positions / out features
#define IIN (OO*128) // 16384
#define EIGEN_KC 248 // Eigen threaded gebp depth panel (validated R5)
#define NPAN 67      // ceil(16384/248)
#define EPSW 1e-4f
#define QCAP 4096

// Scratch (allocation-free rule: __device__ globals)
__device__ float    g_T[(size_t)BB*OO*OO];   // T[b][pos][o], 16.8 MB
__device__ float    g_G[(size_t)OO*BB*OO];   // gumbel noise, 16.8 MB
__device__ float    g_PF[(size_t)BB*OO*OO];  // PF[b][j][o] p-trajectory, 16.8 MB
__device__ int      g_poss[BB*OO];           // chosen position per (b, j)
__device__ int      g_inv[BB*OO];            // step at which column o was chosen
__device__ float    g_lsj[BB*OO];            // per-step logp pieces
__device__ int      g_errj[BB*OO];           // per-step error bits
__device__ int      g_nwork;                 // resolver worklist size
__device__ int4     g_queue[QCAP];           // (b, j, ostar, 0)

// ---------------- Threefry2x32 (bit-exact JAX, partitionable) ----------------
__device__ __forceinline__ uint32_t rotl32(uint32_t x, int d) {
    return (x << d) | (x >> (32 - d));
}

__device__ __forceinline__ void tf2x32(uint32_t k0, uint32_t k1,
                                       uint32_t x0, uint32_t x1,
                                       uint32_t& o0, uint32_t& o1) {
    uint32_t k2 = k0 ^ k1 ^ 0x1BD11BDAu;
    x0 += k0; x1 += k1;
#define TF_R(r) { x0 += x1; x1 = rotl32(x1, r); x1 ^= x0; }
    TF_R(13) TF_R(15) TF_R(26) TF_R(6)
    x0 += k1;  x1 += k2 + 1u;
    TF_R(17) TF_R(29) TF_R(16) TF_R(24)
    x0 += k2;  x1 += k0 + 2u;
    TF_R(13) TF_R(15) TF_R(26) TF_R(6)
    x0 += k0;  x1 += k1 + 3u;
    TF_R(17) TF_R(29) TF_R(16) TF_R(24)
    x0 += k1;  x1 += k2 + 4u;
    TF_R(13) TF_R(15) TF_R(26) TF_R(6)
    x0 += k2;  x1 += k0 + 5u;
#undef TF_R
    o0 = x0; o1 = x1;
}

__device__ __forceinline__ float bits_to_gumbel(uint32_t bits) {
    float f = __uint_as_float((bits >> 9) | 0x3F800000u) - 1.0f;
    float u = fmaxf(1.17549435e-38f, f);
    float t = -logf(u);
    return -logf(t);
}

// ---------------- fused kernel: T GEMM (blocks 0..1023) + gumbel (rest) -----
// k_T body verbatim from the R12 champion; gumbel recomputes keys inline
// (keys[j] = threefry((0,42),(0,j)); bits = o0^o1 of threefry(keys[j],(0,i))).
__global__ __launch_bounds__(256) void k_TG(const float* __restrict__ enc,
                                            const float* __restrict__ W) {
    const int bid = blockIdx.x;
    const int t   = threadIdx.x;

    if (bid >= 1024) {
        // ---- gumbel part ----
        int gb = bid - 1024;              // 0..16383
        int j  = gb >> 7;                 // step
        int i  = (gb & 127) * 256 + t;    // flat element 0..32767
        uint32_t ka, kb;
        tf2x32(0u, 42u, 0u, (uint32_t)j, ka, kb);
        uint32_t o0, o1;
        tf2x32(ka, kb, 0u, (uint32_t)i, o0, o1);
        g_G[(size_t)j * (BB * OO) + i] = bits_to_gumbel(o0 ^ o1);
        return;
    }

    // ---- T part (R12 body) ----
    extern __shared__ float sm[];
    float* Wt = sm;                 // [128][129]
    float* E  = sm + 128 * 129;     // [32][128]
    const int pos = bid >> 3;
    const int b0  = (bid & 7) * 32;

    if (bid == 0 && t == 0) g_nwork = 0;

    for (int i = t; i < 128 * 128; i += 256) {
        int o = i >> 7, d = i & 127;
        Wt[d * 129 + o] = W[(size_t)o * IIN + pos * 128 + d];
    }
    for (int i = t; i < 32 * 128; i += 256) {
        int bb = i >> 7, d = i & 127;
        E[i] = enc[(size_t)(b0 + bb) * IIN + pos * 128 + d];
    }
    __syncthreads();

    const int o  = t & 127;
    const int bg = t >> 7;
    float acc[16];
#pragma unroll
    for (int k = 0; k < 16; k++) acc[k] = 0.f;
    for (int d4 = 0; d4 < 128; d4 += 4) {
        float w0 = Wt[(d4 + 0) * 129 + o];
        float w1 = Wt[(d4 + 1) * 129 + o];
        float w2 = Wt[(d4 + 2) * 129 + o];
        float w3 = Wt[(d4 + 3) * 129 + o];
#pragma unroll
        for (int k = 0; k < 16; k++) {
            float4 e = *(const float4*)&E[(bg * 16 + k) * 128 + d4];
            float a = acc[k];
            a = fmaf(e.x, w0, a);
            a = fmaf(e.y, w1, a);
            a = fmaf(e.z, w2, a);
            a = fmaf(e.w, w3, a);
            acc[k] = a;
        }
    }
#pragma unroll
    for (int k = 0; k < 16; k++) {
        int b = b0 + bg * 16 + k;
        g_T[((size_t)b * 128 + pos) * 128 + o] = acc[k];
    }
}

__device__ __forceinline__ uint32_t ord32(float f) {
    uint32_t fb = __float_as_uint(f);
    return (fb & 0x80000000u) ? ~fb : (fb | 0x80000000u);
}

// ---------------- kernel A: serial sampling chain (warp per row) ------------
__global__ __launch_bounds__(32) void k_sample(const float* __restrict__ bias,
                                               float* __restrict__ out,
                                               int out_size) {
    extern __shared__ float sT[];   // 64KB: T[pos][o]
    const int b    = blockIdx.x;
    const int lane = threadIdx.x;
    const float* Tg = &g_T[(size_t)b * OO * OO];

    {
        const float4* src = (const float4*)Tg;
        float4* dst = (float4*)sT;
#pragma unroll 8
        for (int i = lane; i < 4096; i += 32) dst[i] = src[i];
    }
    __syncwarp();

    // lane owns columns o = 4*lane + q ; Kahan-compensated fp32 p
    float s[4], c[4];
    {
        float4 bv = *(const float4*)&bias[4 * lane];
        s[0] = bv.x; s[1] = bv.y; s[2] = bv.z; s[3] = bv.w;
#pragma unroll
        for (int q = 0; q < 4; q++) c[q] = 0.f;
    }
    for (int pos = 0; pos < 128; pos++) {
        float4 tv = *(const float4*)&sT[pos * 128 + 4 * lane];
        float tq[4] = {tv.x, tv.y, tv.z, tv.w};
#pragma unroll
        for (int q = 0; q < 4; q++) {
            float y = tq[q] - c[q];
            float t = s[q] + y;
            c[q] = (t - s[q]) - y;
            s[q] = t;
        }
    }

    unsigned avail = 0xFu;
    float4 gcur = *(const float4*)&g_G[(size_t)b * 128 + 4 * lane];

    for (int j = 0; j < 128; j++) {
        float4 gnxt = make_float4(0.f, 0.f, 0.f, 0.f);
        if (j < 127)
            gnxt = *(const float4*)&g_G[((size_t)(j + 1) * BB + b) * 128 + 4 * lane];
        float gq[4] = {gcur.x, gcur.y, gcur.z, gcur.w};

        // materialize PF row (off critical path)
        *(float4*)&g_PF[((size_t)b * 128 + j) * 128 + 4 * lane] =
            make_float4(s[0], s[1], s[2], s[3]);

        // lane-local best over 4 owned columns: double-float (hi,lo) key -> u64
        unsigned long long bk = 0ULL; int bi = 0;
#pragma unroll
        for (int q = 0; q < 4; q++) {
            if (avail & (1u << q)) {
                float a = s[q], g = gq[q];
                float th = a + g;
                float bp = th - a;
                float e  = (a - (th - bp)) + (g - bp);
                float te = e - c[q];
                float hi = th + te;
                float lo = te - (hi - th);
                unsigned long long k =
                    ((unsigned long long)ord32(hi) << 32) | ord32(lo);
                if (k > bk) { bk = k; bi = 4 * lane + q; }
            }
        }

        // fast argmax: single REDUX on the hi 32 bits; butterfly only on hi-tie
        int pos;
        {
            uint32_t hi32 = (uint32_t)(bk >> 32);
            uint32_t mh = __reduce_max_sync(0xffffffffu, hi32);
            unsigned msk = __ballot_sync(0xffffffffu, hi32 == mh);
            if (__popc(msk) == 1) {
                pos = __shfl_sync(0xffffffffu, bi, __ffs(msk) - 1);
            } else {
                // exact (hi,lo,idx) butterfly — rare hi-collision path
#pragma unroll
                for (int off = 16; off; off >>= 1) {
                    unsigned long long ok = __shfl_xor_sync(0xffffffffu, bk, off);
                    int oi = __shfl_xor_sync(0xffffffffu, bi, off);
                    if (ok > bk || (ok == bk && oi < bi)) { bk = ok; bi = oi; }
                }
                pos = bi;
            }
        }

        if ((pos >> 2) == lane) avail &= ~(1u << (pos & 3));
        if (lane == 0) {
            g_poss[b * 128 + j] = pos;
            g_inv[b * 128 + pos] = j;
            if (out_size >= BB * OO)
                out[b * 128 + (127 - j)] = (float)pos;
        }

        float4 tv = *(const float4*)&sT[pos * 128 + 4 * lane];
        float tq[4] = {tv.x, tv.y, tv.z, tv.w};
#pragma unroll
        for (int q = 0; q < 4; q++) {
            float y = (-tq[q]) - c[q];
            float t = s[q] + y;
            c[q] = (t - s[q]) - y;
            s[q] = t;
        }
        gcur = gnxt;
    }
}

// ---------------- kernel B: one warp per (b, j), lean strict counting -------
__global__ __launch_bounds__(128) void k_probe(const float* __restrict__ bias) {
    __shared__ __align__(16) float srow[4][128];
    const int t = threadIdx.x, w = t >> 5, lane = t & 31;
    const int item = blockIdx.x * 4 + w;         // 8192 blocks * 4 warps = 32768
    const int b = item >> 7, j = item & 127;

    float4 v = *(const float4*)&g_PF[((size_t)b * 128 + j) * 128 + 4 * lane];
    *(float4*)&srow[w][4 * lane] = v;
    float pf0 = v.x, pf1 = v.y, pf2 = v.z, pf3 = v.w;
    int4 iv = *(const int4*)&g_inv[b * 128 + 4 * lane];
    int av0 = iv.x >= j, av1 = iv.y >= j, av2 = iv.z >= j, av3 = iv.w >= j;
    __syncwarp();

    int cs0 = 0, cs1 = 0, cs2 = 0, cs3 = 0;
    {
        const float4* kr = (const float4*)srow[w];
#pragma unroll 8
        for (int iv4 = 0; iv4 < 32; iv4++) {
            float4 x = kr[iv4];
            cs0 += (x.x > pf0) + (x.y > pf0) + (x.z > pf0) + (x.w > pf0);
            cs1 += (x.x > pf1) + (x.y > pf1) + (x.z > pf1) + (x.w > pf1);
            cs2 += (x.x > pf2) + (x.y > pf2) + (x.z > pf2) + (x.w > pf2);
            cs3 += (x.x > pf3) + (x.y > pf3) + (x.z > pf3) + (x.w > pf3);
        }
    }
    const int o0 = 4 * lane;
    int c1 = 999;
    if (cs0 == j) c1 = min(c1, o0);
    if (cs1 == j) c1 = min(c1, o0 + 1);
    if (cs2 == j) c1 = min(c1, o0 + 2);
    if (cs3 == j) c1 = min(c1, o0 + 3);
#pragma unroll
    for (int off = 16; off; off >>= 1)
        c1 = min(c1, __shfl_xor_sync(0xffffffffu, c1, off));

    int ostar = c1;
    if (c1 == 999) {  // exact stable-rank fallback (duplicates straddle; ~never)
        int ce0 = 0, ce1 = 0, ce2 = 0, ce3 = 0;
        for (int i = 0; i < 128; i++) {
            float x = srow[w][i];
            ce0 += (x == pf0) && (i < o0);
            ce1 += (x == pf1) && (i < o0 + 1);
            ce2 += (x == pf2) && (i < o0 + 2);
            ce3 += (x == pf3) && (i < o0 + 3);
        }
        int c2 = 999;
        if (cs0 + ce0 == j) c2 = min(c2, o0);
        if (cs1 + ce1 == j) c2 = min(c2, o0 + 1);
        if (cs2 + ce2 == j) c2 = min(c2, o0 + 2);
        if (cs3 + ce3 == j) c2 = min(c2, o0 + 3);
#pragma unroll
        for (int off = 16; off; off >>= 1)
            c2 = min(c2, __shfl_xor_sync(0xffffffffu, c2, off));
        ostar = c2;
    }

    const int srcl = ostar >> 2, qsel = ostar & 3;
    float pown = (qsel == 0) ? pf0 : (qsel == 1) ? pf1 : (qsel == 2) ? pf2 : pf3;
    int   aown = (qsel == 0) ? av0 : (qsel == 1) ? av1 : (qsel == 2) ? av2 : av3;
    float pj  = __shfl_sync(0xffffffffu, pown, srcl);
    int   avj = __shfl_sync(0xffffffffu, aown, srcl);

    int mix = ((fabsf(pf0 - pj) < EPSW) && (av0 != avj)) |
              ((fabsf(pf1 - pj) < EPSW) && (av1 != avj)) |
              ((fabsf(pf2 - pj) < EPSW) && (av2 != avj)) |
              ((fabsf(pf3 - pj) < EPSW) && (av3 != avj));
    mix = __any_sync(0xffffffffu, mix);

    float m = -__int_as_float(0x7F800000);
    if (av0) m = fmaxf(m, pf0);
    if (av1) m = fmaxf(m, pf1);
    if (av2) m = fmaxf(m, pf2);
    if (av3) m = fmaxf(m, pf3);
#pragma unroll
    for (int off = 16; off; off >>= 1)
        m = fmaxf(m, __shfl_xor_sync(0xffffffffu, m, off));
    float ss = 0.f;
    if (av0) ss += expf(pf0 - m);
    if (av1) ss += expf(pf1 - m);
    if (av2) ss += expf(pf2 - m);
    if (av3) ss += expf(pf3 - m);
#pragma unroll
    for (int off = 16; off; off >>= 1)
        ss += __shfl_xor_sync(0xffffffffu, ss, off);

    const int posj = g_poss[b * 128 + j];
    const int srcp = posj >> 2, qp = posj & 3;
    float ppw = (qp == 0) ? pf0 : (qp == 1) ? pf1 : (qp == 2) ? pf2 : pf3;
    float ppos = __shfl_sync(0xffffffffu, ppw, srcp);

    if (lane == 0) {
        g_lsj[b * 128 + j]  = ppos - m - logf(ss);
        g_errj[b * 128 + j] = avj ? 0 : 1;
        if (mix) {
            int idx = atomicAdd(&g_nwork, 1);
            if (idx < QCAP) g_queue[idx] = make_int4(b, j, ostar, 0);
        }
    }
}

// ---------------- kernel C: exact resolver, panel-parallel Eigen emulation --
__global__ __launch_bounds__(128) void k_resolve(const float* __restrict__ enc,
                                                 const float* __restrict__ W,
                                                 const float* __restrict__ bias) {
    extern __shared__ float sEnc[];  // [16384]
    __shared__ float row[128];
    __shared__ int   inv[128];
    __shared__ int   incl[128];
    __shared__ float s_pan[NPAN];
    __shared__ unsigned long long key2s[128];
    const int t = threadIdx.x;
    int n = g_nwork; if (n > QCAP) n = QCAP;

    for (int it = blockIdx.x; it < n; it += gridDim.x) {
        int4 e = g_queue[it];
        const int b = e.x, j = e.y, ostar = e.z;
        row[t] = g_PF[((size_t)b * 128 + j) * 128 + t];
        inv[t] = g_inv[b * 128 + t];
        {
            const float4* src = (const float4*)(enc + (size_t)b * IIN);
            float4* dst = (float4*)sEnc;
            for (int i = t; i < IIN / 4; i += 128) dst[i] = src[i];
        }
        __syncthreads();
        float pj = row[ostar];
        int inclt = fabsf(row[t] - pj) < EPSW;
        incl[t] = inclt;
        __syncthreads();

        for (int o = 0; o < 128; o++) {
            if (!incl[o]) continue;
            const float* W_o = W + (size_t)o * IIN;
            if (t < NPAN) {
                int k0 = t * EIGEN_KC;
                int k1 = k0 + EIGEN_KC; if (k1 > IIN) k1 = IIN;
                float acc = 0.f;
                int k = k0;
                while (k < k1) {
                    int pos = k >> 7;
                    int pe  = (pos + 1) << 7; if (pe > k1) pe = k1;
                    if (inv[pos] >= j) {
                        for (; k < pe; k++)
                            acc = fmaf(sEnc[k], W_o[k], acc);
                    } else {
                        k = pe;
                    }
                }
                s_pan[t] = acc;
            }
            __syncthreads();
            if (t == 0) {
                float total = 0.f;
                for (int p = 0; p < NPAN; p++) total += s_pan[p];  // ascending: exact
                float ev = total + bias[o];
                key2s[o] = ((unsigned long long)ord32(ev) << 32) | (unsigned)(127 - o);
            }
            __syncthreads();
        }

        if (inclt) {
            unsigned long long key2 = key2s[t];
            int cm = 0;
            for (int i = 0; i < 128; i++) {
                if (incl[i]) cm += (key2s[i] > key2);
                else         cm += (row[i] > pj);
            }
            if (cm == j) g_errj[b * 128 + j] = (inv[t] >= j) ? 0 : 1;
        }
        __syncthreads();
    }
}

// ---------------- kernel D: final reductions (warp per row) -----------------
__global__ __launch_bounds__(256) void k_final(float* __restrict__ out,
                                               int out_size) {
    const int t = threadIdx.x, lane = t & 31, w = t >> 5;
    const int b = blockIdx.x * 8 + w;           // 32 blocks * 8 warps = 256
    float4 lv = *(const float4*)&g_lsj[b * 128 + 4 * lane];
    int4   ev = *(const int4*)&g_errj[b * 128 + 4 * lane];
    double acc = (double)lv.x + (double)lv.y + (double)lv.z + (double)lv.w;
    int ec = ev.x + ev.y + ev.z + ev.w;
#pragma unroll
    for (int off = 16; off; off >>= 1) {
        acc += __shfl_xor_sync(0xffffffffu, acc, off);
        ec  += __shfl_xor_sync(0xffffffffu, ec, off);
    }
    if (lane == 0) {
        if (out_size >= BB * OO + 2 * BB) {
            out[BB * OO + b]      = (float)acc;
            out[BB * OO + BB + b] = (float)ec;
        } else if (out_size >= BB * OO + BB) {
            out[BB * OO + b] = (float)acc;
        }
    }
}

// ---------------- launch ----------------
extern "C" void kernel_launch(void* const* d_in, const int* in_sizes, int n_in,
                              void* d_out, int out_size) {
    const float* enc  = (const float*)d_in[0];   // [256,128,128]
    const float* W    = (const float*)d_in[1];   // [128,16384]
    const float* bias = (const float*)d_in[2];   // [128]
    float* out = (float*)d_out;

    const int smemTG = (128 * 129 + 32 * 128) * (int)sizeof(float);  // 82432 B
    cudaFuncSetAttribute(k_TG, cudaFuncAttributeMaxDynamicSharedMemorySize, smemTG);
    cudaFuncSetAttribute(k_sample, cudaFuncAttributeMaxDynamicSharedMemorySize, 65536);
    cudaFuncSetAttribute(k_resolve, cudaFuncAttributeMaxDynamicSharedMemorySize, 65536);

    k_TG<<<1024 + 16384, 256, smemTG>>>(enc, W);
    k_sample<<<256, 32, 65536>>>(bias, out, out_size);
    k_probe<<<8192, 128>>>(bias);
    k_resolve<<<256, 128, 65536>>>(enc, W, bias);
    k_final<<<32, 256>>>(out, out_size);
}

// round 16
// speedup vs baseline: 1.2535x; 1.0994x over previous
#include <cuda_runtime.h>
#include <cstdint>

#define BB 256       // batch
#define OO 128       // positions / out features
#define IIN (OO*128) // 16384
#define EIGEN_KC 248 // Eigen threaded gebp depth panel (validated R5)
#define NPAN 67      // ceil(16384/248)
#define EPSW 1e-4f
#define QCAP 4096

// Scratch (allocation-free rule: __device__ globals)
__device__ float    g_T[(size_t)BB*OO*OO];   // T[b][pos][o], 16.8 MB
__device__ float    g_G[(size_t)OO*BB*OO];   // gumbel noise, 16.8 MB
__device__ float    g_PF[(size_t)BB*OO*OO];  // PF[b][j][o] p-trajectory, 16.8 MB
__device__ int      g_poss[BB*OO];           // chosen position per (b, j)
__device__ int      g_inv[BB*OO];            // step at which column o was chosen
__device__ float    g_lsj[BB*OO];            // per-step logp pieces
__device__ int      g_errj[BB*OO];           // per-step error bits
__device__ int      g_nwork;                 // resolver worklist size
__device__ int4     g_queue[QCAP];           // (b, j, ostar, 0)

// ---------------- Threefry2x32 (bit-exact JAX, partitionable) ----------------
__device__ __forceinline__ uint32_t rotl32(uint32_t x, int d) {
    return (x << d) | (x >> (32 - d));
}

__device__ __forceinline__ void tf2x32(uint32_t k0, uint32_t k1,
                                       uint32_t x0, uint32_t x1,
                                       uint32_t& o0, uint32_t& o1) {
    uint32_t k2 = k0 ^ k1 ^ 0x1BD11BDAu;
    x0 += k0; x1 += k1;
#define TF_R(r) { x0 += x1; x1 = rotl32(x1, r); x1 ^= x0; }
    TF_R(13) TF_R(15) TF_R(26) TF_R(6)
    x0 += k1;  x1 += k2 + 1u;
    TF_R(17) TF_R(29) TF_R(16) TF_R(24)
    x0 += k2;  x1 += k0 + 2u;
    TF_R(13) TF_R(15) TF_R(26) TF_R(6)
    x0 += k0;  x1 += k1 + 3u;
    TF_R(17) TF_R(29) TF_R(16) TF_R(24)
    x0 += k1;  x1 += k2 + 4u;
    TF_R(13) TF_R(15) TF_R(26) TF_R(6)
    x0 += k2;  x1 += k0 + 5u;
#undef TF_R
    o0 = x0; o1 = x1;
}

__device__ __forceinline__ float bits_to_gumbel(uint32_t bits) {
    float f = __uint_as_float((bits >> 9) | 0x3F800000u) - 1.0f;
    float u = fmaxf(1.17549435e-38f, f);
    float t = -logf(u);
    return -logf(t);
}

// gumbel with keys inlined (validated bit-identical): no smem, full occupancy
__global__ __launch_bounds__(256) void k_gumbel() {
    int i = blockIdx.x * 256 + threadIdx.x;
    int j = blockIdx.y;
    uint32_t ka, kb;
    tf2x32(0u, 42u, 0u, (uint32_t)j, ka, kb);
    uint32_t o0, o1;
    tf2x32(ka, kb, 0u, (uint32_t)i, o0, o1);
    g_G[(size_t)j * (BB * OO) + i] = bits_to_gumbel(o0 ^ o1);
}

// ---------------- per-position contribution matrix (R12 body) ---------------
__global__ __launch_bounds__(256) void k_T(const float* __restrict__ enc,
                                           const float* __restrict__ W) {
    extern __shared__ float sm[];
    float* Wt = sm;                 // [128][129]
    float* E  = sm + 128 * 129;     // [32][128]
    const int pos = blockIdx.x;
    const int b0  = blockIdx.y * 32;
    const int t   = threadIdx.x;

    if (pos == 0 && blockIdx.y == 0 && t == 0) g_nwork = 0;

    for (int i = t; i < 128 * 128; i += 256) {
        int o = i >> 7, d = i & 127;
        Wt[d * 129 + o] = W[(size_t)o * IIN + pos * 128 + d];
    }
    for (int i = t; i < 32 * 128; i += 256) {
        int bb = i >> 7, d = i & 127;
        E[i] = enc[(size_t)(b0 + bb) * IIN + pos * 128 + d];
    }
    __syncthreads();

    const int o  = t & 127;
    const int bg = t >> 7;
    float acc[16];
#pragma unroll
    for (int k = 0; k < 16; k++) acc[k] = 0.f;
    for (int d4 = 0; d4 < 128; d4 += 4) {
        float w0 = Wt[(d4 + 0) * 129 + o];
        float w1 = Wt[(d4 + 1) * 129 + o];
        float w2 = Wt[(d4 + 2) * 129 + o];
        float w3 = Wt[(d4 + 3) * 129 + o];
#pragma unroll
        for (int k = 0; k < 16; k++) {
            float4 e = *(const float4*)&E[(bg * 16 + k) * 128 + d4];
            float a = acc[k];
            a = fmaf(e.x, w0, a);
            a = fmaf(e.y, w1, a);
            a = fmaf(e.z, w2, a);
            a = fmaf(e.w, w3, a);
            acc[k] = a;
        }
    }
#pragma unroll
    for (int k = 0; k < 16; k++) {
        int b = b0 + bg * 16 + k;
        g_T[((size_t)b * 128 + pos) * 128 + o] = acc[k];
    }
}

__device__ __forceinline__ uint32_t ord32(float f) {
    uint32_t fb = __float_as_uint(f);
    return (fb & 0x80000000u) ? ~fb : (fb | 0x80000000u);
}

// ---------------- kernel A: serial sampling chain (warp per row) ------------
__global__ __launch_bounds__(32) void k_sample(const float* __restrict__ bias,
                                               float* __restrict__ out,
                                               int out_size) {
    extern __shared__ float sT[];   // 64KB: T[pos][o]
    const int b    = blockIdx.x;
    const int lane = threadIdx.x;
    const float* Tg = &g_T[(size_t)b * OO * OO];

    {
        const float4* src = (const float4*)Tg;
        float4* dst = (float4*)sT;
#pragma unroll 8
        for (int i = lane; i < 4096; i += 32) dst[i] = src[i];
    }
    __syncwarp();

    // lane owns columns o = 4*lane + q ; Kahan-compensated fp32 p
    float s[4], c[4];
    {
        float4 bv = *(const float4*)&bias[4 * lane];
        s[0] = bv.x; s[1] = bv.y; s[2] = bv.z; s[3] = bv.w;
#pragma unroll
        for (int q = 0; q < 4; q++) c[q] = 0.f;
    }
    for (int pos = 0; pos < 128; pos++) {
        float4 tv = *(const float4*)&sT[pos * 128 + 4 * lane];
        float tq[4] = {tv.x, tv.y, tv.z, tv.w};
#pragma unroll
        for (int q = 0; q < 4; q++) {
            float y = tq[q] - c[q];
            float t = s[q] + y;
            c[q] = (t - s[q]) - y;
            s[q] = t;
        }
    }

    unsigned avail = 0xFu;
    float4 gcur = *(const float4*)&g_G[(size_t)b * 128 + 4 * lane];

    for (int j = 0; j < 128; j++) {
        float4 gnxt = make_float4(0.f, 0.f, 0.f, 0.f);
        if (j < 127)
            gnxt = *(const float4*)&g_G[((size_t)(j + 1) * BB + b) * 128 + 4 * lane];
        float gq[4] = {gcur.x, gcur.y, gcur.z, gcur.w};

        // materialize PF row (off critical path)
        *(float4*)&g_PF[((size_t)b * 128 + j) * 128 + 4 * lane] =
            make_float4(s[0], s[1], s[2], s[3]);

        // lane-local best over 4 owned columns: double-float (hi,lo) key -> u64
        unsigned long long bk = 0ULL; int bi = 0;
#pragma unroll
        for (int q = 0; q < 4; q++) {
            if (avail & (1u << q)) {
                float a = s[q], g = gq[q];
                float th = a + g;
                float bp = th - a;
                float e  = (a - (th - bp)) + (g - bp);
                float te = e - c[q];
                float hi = th + te;
                float lo = te - (hi - th);
                unsigned long long k =
                    ((unsigned long long)ord32(hi) << 32) | ord32(lo);
                if (k > bk) { bk = k; bi = 4 * lane + q; }
            }
        }

        // fast argmax: single REDUX on the hi 32 bits; butterfly only on hi-tie
        int pos;
        {
            uint32_t hi32 = (uint32_t)(bk >> 32);
            uint32_t mh = __reduce_max_sync(0xffffffffu, hi32);
            unsigned msk = __ballot_sync(0xffffffffu, hi32 == mh);
            if (__popc(msk) == 1) {
                pos = __shfl_sync(0xffffffffu, bi, __ffs(msk) - 1);
            } else {
                // exact (hi,lo,idx) butterfly — rare hi-collision path
#pragma unroll
                for (int off = 16; off; off >>= 1) {
                    unsigned long long ok = __shfl_xor_sync(0xffffffffu, bk, off);
                    int oi = __shfl_xor_sync(0xffffffffu, bi, off);
                    if (ok > bk || (ok == bk && oi < bi)) { bk = ok; bi = oi; }
                }
                pos = bi;
            }
        }

        if ((pos >> 2) == lane) avail &= ~(1u << (pos & 3));
        if (lane == 0) {
            g_poss[b * 128 + j] = pos;
            g_inv[b * 128 + pos] = j;
            if (out_size >= BB * OO)
                out[b * 128 + (127 - j)] = (float)pos;
        }

        float4 tv = *(const float4*)&sT[pos * 128 + 4 * lane];
        float tq[4] = {tv.x, tv.y, tv.z, tv.w};
#pragma unroll
        for (int q = 0; q < 4; q++) {
            float y = (-tq[q]) - c[q];
            float t = s[q] + y;
            c[q] = (t - s[q]) - y;
            s[q] = t;
        }
        gcur = gnxt;
    }
}

// ---------------- kernel B: one warp per (b, j), lean strict counting -------
__global__ __launch_bounds__(128) void k_probe(const float* __restrict__ bias) {
    __shared__ __align__(16) float srow[4][128];
    const int t = threadIdx.x, w = t >> 5, lane = t & 31;
    const int item = blockIdx.x * 4 + w;         // 8192 blocks * 4 warps = 32768
    const int b = item >> 7, j = item & 127;

    float4 v = *(const float4*)&g_PF[((size_t)b * 128 + j) * 128 + 4 * lane];
    *(float4*)&srow[w][4 * lane] = v;
    float pf0 = v.x, pf1 = v.y, pf2 = v.z, pf3 = v.w;
    int4 iv = *(const int4*)&g_inv[b * 128 + 4 * lane];
    int av0 = iv.x >= j, av1 = iv.y >= j, av2 = iv.z >= j, av3 = iv.w >= j;
    __syncwarp();

    int cs0 = 0, cs1 = 0, cs2 = 0, cs3 = 0;
    {
        const float4* kr = (const float4*)srow[w];
#pragma unroll 8
        for (int iv4 = 0; iv4 < 32; iv4++) {
            float4 x = kr[iv4];
            cs0 += (x.x > pf0) + (x.y > pf0) + (x.z > pf0) + (x.w > pf0);
            cs1 += (x.x > pf1) + (x.y > pf1) + (x.z > pf1) + (x.w > pf1);
            cs2 += (x.x > pf2) + (x.y > pf2) + (x.z > pf2) + (x.w > pf2);
            cs3 += (x.x > pf3) + (x.y > pf3) + (x.z > pf3) + (x.w > pf3);
        }
    }
    const int o0 = 4 * lane;
    int c1 = 999;
    if (cs0 == j) c1 = min(c1, o0);
    if (cs1 == j) c1 = min(c1, o0 + 1);
    if (cs2 == j) c1 = min(c1, o0 + 2);
    if (cs3 == j) c1 = min(c1, o0 + 3);
#pragma unroll
    for (int off = 16; off; off >>= 1)
        c1 = min(c1, __shfl_xor_sync(0xffffffffu, c1, off));

    int ostar = c1;
    if (c1 == 999) {  // exact stable-rank fallback (duplicates straddle; ~never)
        int ce0 = 0, ce1 = 0, ce2 = 0, ce3 = 0;
        for (int i = 0; i < 128; i++) {
            float x = srow[w][i];
            ce0 += (x == pf0) && (i < o0);
            ce1 += (x == pf1) && (i < o0 + 1);
            ce2 += (x == pf2) && (i < o0 + 2);
            ce3 += (x == pf3) && (i < o0 + 3);
        }
        int c2 = 999;
        if (cs0 + ce0 == j) c2 = min(c2, o0);
        if (cs1 + ce1 == j) c2 = min(c2, o0 + 1);
        if (cs2 + ce2 == j) c2 = min(c2, o0 + 2);
        if (cs3 + ce3 == j) c2 = min(c2, o0 + 3);
#pragma unroll
        for (int off = 16; off; off >>= 1)
            c2 = min(c2, __shfl_xor_sync(0xffffffffu, c2, off));
        ostar = c2;
    }

    const int srcl = ostar >> 2, qsel = ostar & 3;
    float pown = (qsel == 0) ? pf0 : (qsel == 1) ? pf1 : (qsel == 2) ? pf2 : pf3;
    int   aown = (qsel == 0) ? av0 : (qsel == 1) ? av1 : (qsel == 2) ? av2 : av3;
    float pj  = __shfl_sync(0xffffffffu, pown, srcl);
    int   avj = __shfl_sync(0xffffffffu, aown, srcl);

    int mix = ((fabsf(pf0 - pj) < EPSW) && (av0 != avj)) |
              ((fabsf(pf1 - pj) < EPSW) && (av1 != avj)) |
              ((fabsf(pf2 - pj) < EPSW) && (av2 != avj)) |
              ((fabsf(pf3 - pj) < EPSW) && (av3 != avj));
    mix = __any_sync(0xffffffffu, mix);

    float m = -__int_as_float(0x7F800000);
    if (av0) m = fmaxf(m, pf0);
    if (av1) m = fmaxf(m, pf1);
    if (av2) m = fmaxf(m, pf2);
    if (av3) m = fmaxf(m, pf3);
#pragma unroll
    for (int off = 16; off; off >>= 1)
        m = fmaxf(m, __shfl_xor_sync(0xffffffffu, m, off));
    float ss = 0.f;
    if (av0) ss += expf(pf0 - m);
    if (av1) ss += expf(pf1 - m);
    if (av2) ss += expf(pf2 - m);
    if (av3) ss += expf(pf3 - m);
#pragma unroll
    for (int off = 16; off; off >>= 1)
        ss += __shfl_xor_sync(0xffffffffu, ss, off);

    const int posj = g_poss[b * 128 + j];
    const int srcp = posj >> 2, qp = posj & 3;
    float ppw = (qp == 0) ? pf0 : (qp == 1) ? pf1 : (qp == 2) ? pf2 : pf3;
    float ppos = __shfl_sync(0xffffffffu, ppw, srcp);

    if (lane == 0) {
        g_lsj[b * 128 + j]  = ppos - m - logf(ss);
        g_errj[b * 128 + j] = avj ? 0 : 1;
        if (mix) {
            int idx = atomicAdd(&g_nwork, 1);
            if (idx < QCAP) g_queue[idx] = make_int4(b, j, ostar, 0);
        }
    }
}

// ---------------- kernel C: exact resolver, warp-parallel columns -----------
// Same Eigen-kc248 arithmetic (ascending-k FMA per panel, ascending panel sum)
// with float4 loads (all segment bounds are multiples of 4 floats) and one
// warp per incl-column (4 concurrent); lanes cover panels lane, +32, +64.
__global__ __launch_bounds__(128) void k_resolve(const float* __restrict__ enc,
                                                 const float* __restrict__ W,
                                                 const float* __restrict__ bias) {
    extern __shared__ float sEnc[];  // [16384]
    __shared__ float row[128];
    __shared__ int   inv[128];
    __shared__ int   incl[128];
    __shared__ int   olist[128];
    __shared__ int   s_cnt;
    __shared__ float s_pan[4][NPAN + 1];
    __shared__ unsigned long long key2s[128];
    const int t = threadIdx.x, w = t >> 5, lane = t & 31;
    int n = g_nwork; if (n > QCAP) n = QCAP;

    for (int it = blockIdx.x; it < n; it += gridDim.x) {
        int4 e = g_queue[it];
        const int b = e.x, j = e.y, ostar = e.z;
        row[t] = g_PF[((size_t)b * 128 + j) * 128 + t];
        inv[t] = g_inv[b * 128 + t];
        if (t == 0) s_cnt = 0;
        {
            const float4* src = (const float4*)(enc + (size_t)b * IIN);
            float4* dst = (float4*)sEnc;
            for (int i = t; i < IIN / 4; i += 128) dst[i] = src[i];
        }
        __syncthreads();
        float pj = row[ostar];
        int inclt = fabsf(row[t] - pj) < EPSW;
        incl[t] = inclt;
        if (inclt) {
            int idx = atomicAdd(&s_cnt, 1);
            olist[idx] = t;   // order within list irrelevant (keys are per-o)
        }
        __syncthreads();
        const int cnt = s_cnt;

        for (int ob = w; ob < cnt; ob += 4) {
            const int o = olist[ob];
            const float* W_o = W + (size_t)o * IIN;
#pragma unroll
            for (int rep = 0; rep < 3; rep++) {
                int pp = lane + rep * 32;
                if (pp >= NPAN) break;
                int k0 = pp * EIGEN_KC;
                int k1 = k0 + EIGEN_KC; if (k1 > IIN) k1 = IIN;
                float acc = 0.f;
                int k = k0;
                while (k < k1) {
                    int pos = k >> 7;
                    int pe  = (pos + 1) << 7; if (pe > k1) pe = k1;
                    if (inv[pos] >= j) {
                        for (; k < pe; k += 4) {
                            float4 ev = *(const float4*)&sEnc[k];
                            float4 wv = *(const float4*)&W_o[k];
                            acc = fmaf(ev.x, wv.x, acc);
                            acc = fmaf(ev.y, wv.y, acc);
                            acc = fmaf(ev.z, wv.z, acc);
                            acc = fmaf(ev.w, wv.w, acc);
                        }
                    } else {
                        k = pe;
                    }
                }
                s_pan[w][pp] = acc;
            }
            __syncwarp();
            if (lane == 0) {
                float total = 0.f;
                for (int p = 0; p < NPAN; p++) total += s_pan[w][p];  // ascending
                float ev = total + bias[o];
                key2s[o] = ((unsigned long long)ord32(ev) << 32) | (unsigned)(127 - o);
            }
            __syncwarp();
        }
        __syncthreads();

        if (inclt) {
            unsigned long long key2 = key2s[t];
            int cm = 0;
            for (int i = 0; i < 128; i++) {
                if (incl[i]) cm += (key2s[i] > key2);
                else         cm += (row[i] > pj);
            }
            if (cm == j) g_errj[b * 128 + j] = (inv[t] >= j) ? 0 : 1;
        }
        __syncthreads();
    }
}

// ---------------- kernel D: final reductions (warp per row) -----------------
__global__ __launch_bounds__(256) void k_final(float* __restrict__ out,
                                               int out_size) {
    const int t = threadIdx.x, lane = t & 31, w = t >> 5;
    const int b = blockIdx.x * 8 + w;           // 32 blocks * 8 warps = 256
    float4 lv = *(const float4*)&g_lsj[b * 128 + 4 * lane];
    int4   ev = *(const int4*)&g_errj[b * 128 + 4 * lane];
    double acc = (double)lv.x + (double)lv.y + (double)lv.z + (double)lv.w;
    int ec = ev.x + ev.y + ev.z + ev.w;
#pragma unroll
    for (int off = 16; off; off >>= 1) {
        acc += __shfl_xor_sync(0xffffffffu, acc, off);
        ec  += __shfl_xor_sync(0xffffffffu, ec, off);
    }
    if (lane == 0) {
        if (out_size >= BB * OO + 2 * BB) {
            out[BB * OO + b]      = (float)acc;
            out[BB * OO + BB + b] = (float)ec;
        } else if (out_size >= BB * OO + BB) {
            out[BB * OO + b] = (float)acc;
        }
    }
}

// ---------------- launch ----------------
extern "C" void kernel_launch(void* const* d_in, const int* in_sizes, int n_in,
                              void* d_out, int out_size) {
    const float* enc  = (const float*)d_in[0];   // [256,128,128]
    const float* W    = (const float*)d_in[1];   // [128,16384]
    const float* bias = (const float*)d_in[2];   // [128]
    float* out = (float*)d_out;

    const int smemT = (128 * 129 + 32 * 128) * (int)sizeof(float);  // 82432 B
    cudaFuncSetAttribute(k_T, cudaFuncAttributeMaxDynamicSharedMemorySize, smemT);
    cudaFuncSetAttribute(k_sample, cudaFuncAttributeMaxDynamicSharedMemorySize, 65536);
    cudaFuncSetAttribute(k_resolve, cudaFuncAttributeMaxDynamicSharedMemorySize, 65536);

    k_T<<<dim3(128, 8), 256, smemT>>>(enc, W);
    k_gumbel<<<dim3(128, 128), 256>>>();
    k_sample<<<256, 32, 65536>>>(bias, out, out_size);
    k_probe<<<8192, 128>>>(bias);
    k_resolve<<<256, 128, 65536>>>(enc, W, bias);
    k_final<<<32, 256>>>(out, out_size);
}

// round 17
// speedup vs baseline: 1.3990x; 1.1161x over previous
#include <cuda_runtime.h>
#include <cstdint>

#define BB 256       // batch
#define OO 128       // positions / out features
#define IIN (OO*128) // 16384
#define EIGEN_KC 248 // Eigen threaded gebp depth panel (validated R5)
#define NPAN 67      // ceil(16384/248)
#define EPSW 1e-4f
#define QCAP 4096

// Scratch (allocation-free rule: __device__ globals)
__device__ float    g_T[(size_t)BB*OO*OO];   // T[b][pos][o], 16.8 MB
__device__ float    g_G[(size_t)OO*BB*OO];   // gumbel noise, 16.8 MB
__device__ float    g_PF[(size_t)BB*OO*OO];  // PF[b][j][o] p-trajectory, 16.8 MB
__device__ int      g_poss[BB*OO];           // chosen position per (b, j)
__device__ int      g_inv[BB*OO];            // step at which column o was chosen
__device__ float    g_lsj[BB*OO];            // per-step logp pieces
__device__ int      g_errj[BB*OO];           // per-step error bits
__device__ int      g_nwork;                 // resolver worklist size
__device__ int4     g_queue[QCAP];           // (b, j, ostar, 0)

// ---------------- Threefry2x32 (bit-exact JAX, partitionable) ----------------
__device__ __forceinline__ uint32_t rotl32(uint32_t x, int d) {
    return (x << d) | (x >> (32 - d));
}

__device__ __forceinline__ void tf2x32(uint32_t k0, uint32_t k1,
                                       uint32_t x0, uint32_t x1,
                                       uint32_t& o0, uint32_t& o1) {
    uint32_t k2 = k0 ^ k1 ^ 0x1BD11BDAu;
    x0 += k0; x1 += k1;
#define TF_R(r) { x0 += x1; x1 = rotl32(x1, r); x1 ^= x0; }
    TF_R(13) TF_R(15) TF_R(26) TF_R(6)
    x0 += k1;  x1 += k2 + 1u;
    TF_R(17) TF_R(29) TF_R(16) TF_R(24)
    x0 += k2;  x1 += k0 + 2u;
    TF_R(13) TF_R(15) TF_R(26) TF_R(6)
    x0 += k0;  x1 += k1 + 3u;
    TF_R(17) TF_R(29) TF_R(16) TF_R(24)
    x0 += k1;  x1 += k2 + 4u;
    TF_R(13) TF_R(15) TF_R(26) TF_R(6)
    x0 += k2;  x1 += k0 + 5u;
#undef TF_R
    o0 = x0; o1 = x1;
}

__device__ __forceinline__ float bits_to_gumbel(uint32_t bits) {
    float f = __uint_as_float((bits >> 9) | 0x3F800000u) - 1.0f;
    float u = fmaxf(1.17549435e-38f, f);
    float t = -logf(u);
    return -logf(t);
}

// ---------------- fused: T GEMM + this block's gumbel slice -----------------
// Block (pos, by): T tile body (R12, validated) + gumbel for j = pos,
// i = by*4096 + e*256 + t (e = 0..15). ALU/MUFU gumbel work fills the idle
// issue slots of the FFMA-bound GEMM. Values bit-identical to split kernels.
__global__ __launch_bounds__(256) void k_T(const float* __restrict__ enc,
                                           const float* __restrict__ W) {
    extern __shared__ float sm[];
    float* Wt = sm;                 // [128][129]
    float* E  = sm + 128 * 129;     // [32][128]
    const int pos = blockIdx.x;
    const int b0  = blockIdx.y * 32;
    const int t   = threadIdx.x;

    if (pos == 0 && blockIdx.y == 0 && t == 0) g_nwork = 0;

    for (int i = t; i < 128 * 128; i += 256) {
        int o = i >> 7, d = i & 127;
        Wt[d * 129 + o] = W[(size_t)o * IIN + pos * 128 + d];
    }
    for (int i = t; i < 32 * 128; i += 256) {
        int bb = i >> 7, d = i & 127;
        E[i] = enc[(size_t)(b0 + bb) * IIN + pos * 128 + d];
    }

    // ---- gumbel slice (before barrier: overlaps the smem-load latency) ----
    {
        const int j = pos;
        uint32_t ka, kb;
        tf2x32(0u, 42u, 0u, (uint32_t)j, ka, kb);
        const int ibase = blockIdx.y * 4096 + t;
#pragma unroll 4
        for (int e = 0; e < 16; e++) {
            int i = ibase + e * 256;
            uint32_t o0, o1;
            tf2x32(ka, kb, 0u, (uint32_t)i, o0, o1);
            g_G[(size_t)j * (BB * OO) + i] = bits_to_gumbel(o0 ^ o1);
        }
    }
    __syncthreads();

    const int o  = t & 127;
    const int bg = t >> 7;
    float acc[16];
#pragma unroll
    for (int k = 0; k < 16; k++) acc[k] = 0.f;
    for (int d4 = 0; d4 < 128; d4 += 4) {
        float w0 = Wt[(d4 + 0) * 129 + o];
        float w1 = Wt[(d4 + 1) * 129 + o];
        float w2 = Wt[(d4 + 2) * 129 + o];
        float w3 = Wt[(d4 + 3) * 129 + o];
#pragma unroll
        for (int k = 0; k < 16; k++) {
            float4 e = *(const float4*)&E[(bg * 16 + k) * 128 + d4];
            float a = acc[k];
            a = fmaf(e.x, w0, a);
            a = fmaf(e.y, w1, a);
            a = fmaf(e.z, w2, a);
            a = fmaf(e.w, w3, a);
            acc[k] = a;
        }
    }
#pragma unroll
    for (int k = 0; k < 16; k++) {
        int b = b0 + bg * 16 + k;
        g_T[((size_t)b * 128 + pos) * 128 + o] = acc[k];
    }
}

__device__ __forceinline__ uint32_t ord32(float f) {
    uint32_t fb = __float_as_uint(f);
    return (fb & 0x80000000u) ? ~fb : (fb | 0x80000000u);
}

// ---------------- kernel A: serial sampling chain (warp per row) ------------
__global__ __launch_bounds__(32) void k_sample(const float* __restrict__ bias,
                                               float* __restrict__ out,
                                               int out_size) {
    extern __shared__ float sT[];   // 64KB: T[pos][o]
    const int b    = blockIdx.x;
    const int lane = threadIdx.x;
    const float* Tg = &g_T[(size_t)b * OO * OO];

    {
        const float4* src = (const float4*)Tg;
        float4* dst = (float4*)sT;
#pragma unroll 8
        for (int i = lane; i < 4096; i += 32) dst[i] = src[i];
    }
    __syncwarp();

    // lane owns columns o = 4*lane + q ; Kahan-compensated fp32 p
    float s[4], c[4];
    {
        float4 bv = *(const float4*)&bias[4 * lane];
        s[0] = bv.x; s[1] = bv.y; s[2] = bv.z; s[3] = bv.w;
#pragma unroll
        for (int q = 0; q < 4; q++) c[q] = 0.f;
    }
    for (int pos = 0; pos < 128; pos++) {
        float4 tv = *(const float4*)&sT[pos * 128 + 4 * lane];
        float tq[4] = {tv.x, tv.y, tv.z, tv.w};
#pragma unroll
        for (int q = 0; q < 4; q++) {
            float y = tq[q] - c[q];
            float t = s[q] + y;
            c[q] = (t - s[q]) - y;
            s[q] = t;
        }
    }

    unsigned avail = 0xFu;
    float4 gcur = *(const float4*)&g_G[(size_t)b * 128 + 4 * lane];

    for (int j = 0; j < 128; j++) {
        float4 gnxt = make_float4(0.f, 0.f, 0.f, 0.f);
        if (j < 127)
            gnxt = *(const float4*)&g_G[((size_t)(j + 1) * BB + b) * 128 + 4 * lane];
        float gq[4] = {gcur.x, gcur.y, gcur.z, gcur.w};

        // materialize PF row (off critical path)
        *(float4*)&g_PF[((size_t)b * 128 + j) * 128 + 4 * lane] =
            make_float4(s[0], s[1], s[2], s[3]);

        // lane-local best over 4 owned columns: double-float (hi,lo) key -> u64
        unsigned long long bk = 0ULL; int bi = 0;
#pragma unroll
        for (int q = 0; q < 4; q++) {
            if (avail & (1u << q)) {
                float a = s[q], g = gq[q];
                float th = a + g;
                float bp = th - a;
                float e  = (a - (th - bp)) + (g - bp);
                float te = e - c[q];
                float hi = th + te;
                float lo = te - (hi - th);
                unsigned long long k =
                    ((unsigned long long)ord32(hi) << 32) | ord32(lo);
                if (k > bk) { bk = k; bi = 4 * lane + q; }
            }
        }

        // fast argmax: REDUX.MAX on hi32; parallel REDUX min/add resolve winner
        int pos;
        {
            uint32_t hi32 = (uint32_t)(bk >> 32);
            uint32_t mh = __reduce_max_sync(0xffffffffu, hi32);
            int eq = (hi32 == mh);
            int minidx = __reduce_min_sync(0xffffffffu, eq ? bi : 1023);
            int cnt    = __reduce_add_sync(0xffffffffu, eq);
            if (cnt == 1) {
                pos = minidx;
            } else {
                // exact (hi,lo,idx) butterfly — rare hi-collision path
#pragma unroll
                for (int off = 16; off; off >>= 1) {
                    unsigned long long ok = __shfl_xor_sync(0xffffffffu, bk, off);
                    int oi = __shfl_xor_sync(0xffffffffu, bi, off);
                    if (ok > bk || (ok == bk && oi < bi)) { bk = ok; bi = oi; }
                }
                pos = bi;
            }
        }

        if ((pos >> 2) == lane) avail &= ~(1u << (pos & 3));
        if (lane == 0) {
            g_poss[b * 128 + j] = pos;
            g_inv[b * 128 + pos] = j;
            if (out_size >= BB * OO)
                out[b * 128 + (127 - j)] = (float)pos;
        }

        float4 tv = *(const float4*)&sT[pos * 128 + 4 * lane];
        float tq[4] = {tv.x, tv.y, tv.z, tv.w};
#pragma unroll
        for (int q = 0; q < 4; q++) {
            float y = (-tq[q]) - c[q];
            float t = s[q] + y;
            c[q] = (t - s[q]) - y;
            s[q] = t;
        }
        gcur = gnxt;
    }
}

// ---------------- kernel B: one warp per (b, j), lean strict counting -------
__global__ __launch_bounds__(128) void k_probe(const float* __restrict__ bias) {
    __shared__ __align__(16) float srow[4][128];
    const int t = threadIdx.x, w = t >> 5, lane = t & 31;
    const int item = blockIdx.x * 4 + w;         // 8192 blocks * 4 warps = 32768
    const int b = item >> 7, j = item & 127;

    float4 v = *(const float4*)&g_PF[((size_t)b * 128 + j) * 128 + 4 * lane];
    *(float4*)&srow[w][4 * lane] = v;
    float pf0 = v.x, pf1 = v.y, pf2 = v.z, pf3 = v.w;
    int4 iv = *(const int4*)&g_inv[b * 128 + 4 * lane];
    int av0 = iv.x >= j, av1 = iv.y >= j, av2 = iv.z >= j, av3 = iv.w >= j;
    __syncwarp();

    int cs0 = 0, cs1 = 0, cs2 = 0, cs3 = 0;
    {
        const float4* kr = (const float4*)srow[w];
#pragma unroll 8
        for (int iv4 = 0; iv4 < 32; iv4++) {
            float4 x = kr[iv4];
            cs0 += (x.x > pf0) + (x.y > pf0) + (x.z > pf0) + (x.w > pf0);
            cs1 += (x.x > pf1) + (x.y > pf1) + (x.z > pf1) + (x.w > pf1);
            cs2 += (x.x > pf2) + (x.y > pf2) + (x.z > pf2) + (x.w > pf2);
            cs3 += (x.x > pf3) + (x.y > pf3) + (x.z > pf3) + (x.w > pf3);
        }
    }
    const int o0 = 4 * lane;
    int c1 = 999;
    if (cs0 == j) c1 = min(c1, o0);
    if (cs1 == j) c1 = min(c1, o0 + 1);
    if (cs2 == j) c1 = min(c1, o0 + 2);
    if (cs3 == j) c1 = min(c1, o0 + 3);
#pragma unroll
    for (int off = 16; off; off >>= 1)
        c1 = min(c1, __shfl_xor_sync(0xffffffffu, c1, off));

    int ostar = c1;
    if (c1 == 999) {  // exact stable-rank fallback (duplicates straddle; ~never)
        int ce0 = 0, ce1 = 0, ce2 = 0, ce3 = 0;
        for (int i = 0; i < 128; i++) {
            float x = srow[w][i];
            ce0 += (x == pf0) && (i < o0);
            ce1 += (x == pf1) && (i < o0 + 1);
            ce2 += (x == pf2) && (i < o0 + 2);
            ce3 += (x == pf3) && (i < o0 + 3);
        }
        int c2 = 999;
        if (cs0 + ce0 == j) c2 = min(c2, o0);
        if (cs1 + ce1 == j) c2 = min(c2, o0 + 1);
        if (cs2 + ce2 == j) c2 = min(c2, o0 + 2);
        if (cs3 + ce3 == j) c2 = min(c2, o0 + 3);
#pragma unroll
        for (int off = 16; off; off >>= 1)
            c2 = min(c2, __shfl_xor_sync(0xffffffffu, c2, off));
        ostar = c2;
    }

    const int srcl = ostar >> 2, qsel = ostar & 3;
    float pown = (qsel == 0) ? pf0 : (qsel == 1) ? pf1 : (qsel == 2) ? pf2 : pf3;
    int   aown = (qsel == 0) ? av0 : (qsel == 1) ? av1 : (qsel == 2) ? av2 : av3;
    float pj  = __shfl_sync(0xffffffffu, pown, srcl);
    int   avj = __shfl_sync(0xffffffffu, aown, srcl);

    int mix = ((fabsf(pf0 - pj) < EPSW) && (av0 != avj)) |
              ((fabsf(pf1 - pj) < EPSW) && (av1 != avj)) |
              ((fabsf(pf2 - pj) < EPSW) && (av2 != avj)) |
              ((fabsf(pf3 - pj) < EPSW) && (av3 != avj));
    mix = __any_sync(0xffffffffu, mix);

    float m = -__int_as_float(0x7F800000);
    if (av0) m = fmaxf(m, pf0);
    if (av1) m = fmaxf(m, pf1);
    if (av2) m = fmaxf(m, pf2);
    if (av3) m = fmaxf(m, pf3);
#pragma unroll
    for (int off = 16; off; off >>= 1)
        m = fmaxf(m, __shfl_xor_sync(0xffffffffu, m, off));
    float ss = 0.f;
    if (av0) ss += expf(pf0 - m);
    if (av1) ss += expf(pf1 - m);
    if (av2) ss += expf(pf2 - m);
    if (av3) ss += expf(pf3 - m);
#pragma unroll
    for (int off = 16; off; off >>= 1)
        ss += __shfl_xor_sync(0xffffffffu, ss, off);

    const int posj = g_poss[b * 128 + j];
    const int srcp = posj >> 2, qp = posj & 3;
    float ppw = (qp == 0) ? pf0 : (qp == 1) ? pf1 : (qp == 2) ? pf2 : pf3;
    float ppos = __shfl_sync(0xffffffffu, ppw, srcp);

    if (lane == 0) {
        g_lsj[b * 128 + j]  = ppos - m - logf(ss);
        g_errj[b * 128 + j] = avj ? 0 : 1;
        if (mix) {
            int idx = atomicAdd(&g_nwork, 1);
            if (idx < QCAP) g_queue[idx] = make_int4(b, j, ostar, 0);
        }
    }
}

// ---------------- kernel C: exact resolver, warp-parallel columns -----------
__global__ __launch_bounds__(128) void k_resolve(const float* __restrict__ enc,
                                                 const float* __restrict__ W,
                                                 const float* __restrict__ bias) {
    extern __shared__ float sEnc[];  // [16384]
    __shared__ float row[128];
    __shared__ int   inv[128];
    __shared__ int   incl[128];
    __shared__ int   olist[128];
    __shared__ int   s_cnt;
    __shared__ float s_pan[4][NPAN + 1];
    __shared__ unsigned long long key2s[128];
    const int t = threadIdx.x, w = t >> 5, lane = t & 31;
    int n = g_nwork; if (n > QCAP) n = QCAP;

    for (int it = blockIdx.x; it < n; it += gridDim.x) {
        int4 e = g_queue[it];
        const int b = e.x, j = e.y, ostar = e.z;
        row[t] = g_PF[((size_t)b * 128 + j) * 128 + t];
        inv[t] = g_inv[b * 128 + t];
        if (t == 0) s_cnt = 0;
        {
            const float4* src = (const float4*)(enc + (size_t)b * IIN);
            float4* dst = (float4*)sEnc;
            for (int i = t; i < IIN / 4; i += 128) dst[i] = src[i];
        }
        __syncthreads();
        float pj = row[ostar];
        int inclt = fabsf(row[t] - pj) < EPSW;
        incl[t] = inclt;
        if (inclt) {
            int idx = atomicAdd(&s_cnt, 1);
            olist[idx] = t;
        }
        __syncthreads();
        const int cnt = s_cnt;

        for (int ob = w; ob < cnt; ob += 4) {
            const int o = olist[ob];
            const float* W_o = W + (size_t)o * IIN;
#pragma unroll
            for (int rep = 0; rep < 3; rep++) {
                int pp = lane + rep * 32;
                if (pp >= NPAN) break;
                int k0 = pp * EIGEN_KC;
                int k1 = k0 + EIGEN_KC; if (k1 > IIN) k1 = IIN;
                float acc = 0.f;
                int k = k0;
                while (k < k1) {
                    int pos = k >> 7;
                    int pe  = (pos + 1) << 7; if (pe > k1) pe = k1;
                    if (inv[pos] >= j) {
                        for (; k < pe; k += 4) {
                            float4 ev = *(const float4*)&sEnc[k];
                            float4 wv = *(const float4*)&W_o[k];
                            acc = fmaf(ev.x, wv.x, acc);
                            acc = fmaf(ev.y, wv.y, acc);
                            acc = fmaf(ev.z, wv.z, acc);
                            acc = fmaf(ev.w, wv.w, acc);
                        }
                    } else {
                        k = pe;
                    }
                }
                s_pan[w][pp] = acc;
            }
            __syncwarp();
            if (lane == 0) {
                float total = 0.f;
                for (int p = 0; p < NPAN; p++) total += s_pan[w][p];  // ascending
                float ev = total + bias[o];
                key2s[o] = ((unsigned long long)ord32(ev) << 32) | (unsigned)(127 - o);
            }
            __syncwarp();
        }
        __syncthreads();

        if (inclt) {
            unsigned long long key2 = key2s[t];
            int cm = 0;
            for (int i = 0; i < 128; i++) {
                if (incl[i]) cm += (key2s[i] > key2);
                else         cm += (row[i] > pj);
            }
            if (cm == j) g_errj[b * 128 + j] = (inv[t] >= j) ? 0 : 1;
        }
        __syncthreads();
    }
}

// ---------------- kernel D: final reductions (warp per row) -----------------
__global__ __launch_bounds__(256) void k_final(float* __restrict__ out,
                                               int out_size) {
    const int t = threadIdx.x, lane = t & 31, w = t >> 5;
    const int b = blockIdx.x * 8 + w;           // 32 blocks * 8 warps = 256
    float4 lv = *(const float4*)&g_lsj[b * 128 + 4 * lane];
    int4   ev = *(const int4*)&g_errj[b * 128 + 4 * lane];
    double acc = (double)lv.x + (double)lv.y + (double)lv.z + (double)lv.w;
    int ec = ev.x + ev.y + ev.z + ev.w;
#pragma unroll
    for (int off = 16; off; off >>= 1) {
        acc += __shfl_xor_sync(0xffffffffu, acc, off);
        ec  += __shfl_xor_sync(0xffffffffu, ec, off);
    }
    if (lane == 0) {
        if (out_size >= BB * OO + 2 * BB) {
            out[BB * OO + b]      = (float)acc;
            out[BB * OO + BB + b] = (float)ec;
        } else if (out_size >= BB * OO + BB) {
            out[BB * OO + b] = (float)acc;
        }
    }
}

// ---------------- launch ----------------
extern "C" void kernel_launch(void* const* d_in, const int* in_sizes, int n_in,
                              void* d_out, int out_size) {
    const float* enc  = (const float*)d_in[0];   // [256,128,128]
    const float* W    = (const float*)d_in[1];   // [128,16384]
    const float* bias = (const float*)d_in[2];   // [128]
    float* out = (float*)d_out;

    const int smemT = (128 * 129 + 32 * 128) * (int)sizeof(float);  // 82432 B
    cudaFuncSetAttribute(k_T, cudaFuncAttributeMaxDynamicSharedMemorySize, smemT);
    cudaFuncSetAttribute(k_sample, cudaFuncAttributeMaxDynamicSharedMemorySize, 65536);
    cudaFuncSetAttribute(k_resolve, cudaFuncAttributeMaxDynamicSharedMemorySize, 65536);

    k_T<<<dim3(128, 8), 256, smemT>>>(enc, W);
    k_sample<<<256, 32, 65536>>>(bias, out, out_size);
    k_probe<<<8192, 128>>>(bias);
    k_resolve<<<256, 128, 65536>>>(enc, W, bias);
    k_final<<<32, 256>>>(out, out_size);
}